// round 10
// baseline (speedup 1.0000x reference)
#include <cuda_runtime.h>
#include <cuda_bf16.h>

#define NN 50000
#define NP 50048
#define EE 800000
#define LL 4
#define MAXY 5
#define MAXT 4

// ---------------- packed bf16 hi/lo storage ----------------
__device__ unsigned g_h[NP * 64];
__device__ unsigned g_h2[NP * 64];
__device__ unsigned g_p[NP * 64];
__device__ unsigned g_p2[NP * 64];
__device__ unsigned g_EA[NP * 64];
__device__ unsigned g_EA2[NP * 64];
__device__ unsigned g_EB[NP * 64];
__device__ unsigned g_EB2[NP * 64];
__device__ unsigned g_S[NP * 64];
__device__ unsigned g_R[NP * 64];
__device__ unsigned g_agg[NP * 64];
__device__ unsigned g_hin[NP * 128];
__device__ unsigned g_pin[NP * 16];
__device__ unsigned g_w[110 * 8192];      // 54 direct + 56 composed slots
__device__ float g_cw[16 * 4096];         // fp32 workspace (CA1,CA2,CB1,CB2 per layer)
__device__ float g_bias[26 * 64];         // composed bias vectors
__device__ float g_esum[NN * 16];
__device__ int   g_deg[NN];
__device__ int   g_rowptr[NN + 1];
__device__ int   g_cursor[NN];
__device__ int   g_col[EE];
__device__ int   g_eid[EE];
__device__ float g_Gh[LL * 16 * 64];
__device__ float g_ch[LL * 64];
__device__ float g_Gp[LL * 16 * 64];
__device__ float g_cp[LL * 64];

// ---------------- helpers ----------------
__device__ __forceinline__ float2 unpk(uint2 v) {
    __nv_bfloat162 h = *(__nv_bfloat162*)&v.x;
    __nv_bfloat162 l = *(__nv_bfloat162*)&v.y;
    return make_float2(__bfloat162float(h.x) + __bfloat162float(l.x),
                       __bfloat162float(h.y) + __bfloat162float(l.y));
}
__device__ __forceinline__ uint2 pk(float a, float b) {
    __nv_bfloat16 ha = __float2bfloat16_rn(a), hb = __float2bfloat16_rn(b);
    float la = a - __bfloat162float(ha), lb = b - __bfloat162float(hb);
    __nv_bfloat162 hw; hw.x = ha; hw.y = hb;
    __nv_bfloat162 lw; lw.x = __float2bfloat16_rn(la); lw.y = __float2bfloat16_rn(lb);
    uint2 r; r.x = *(unsigned*)&hw; r.y = *(unsigned*)&lw; return r;
}
__device__ __forceinline__ void mma_bf16(float* d, const unsigned* a, const unsigned* b) {
    asm volatile(
        "mma.sync.aligned.m16n8k16.row.col.f32.bf16.bf16.f32 "
        "{%0,%1,%2,%3}, {%4,%5,%6,%7}, {%8,%9}, {%0,%1,%2,%3};"
        : "+f"(d[0]), "+f"(d[1]), "+f"(d[2]), "+f"(d[3])
        : "r"(a[0]), "r"(a[1]), "r"(a[2]), "r"(a[3]), "r"(b[0]), "r"(b[1]));
}

// ---------------- setup kernels ----------------
__global__ void out_kernel(float* __restrict__ out, const unsigned* __restrict__ hc,
                           const unsigned* __restrict__ pc) {
    int i = blockIdx.x * blockDim.x + threadIdx.x;
    if (i >= NN * 32) return;
    int r = i >> 5, j = i & 31;
    float2 fh = unpk(*(const uint2*)&hc[(size_t)r * 64 + j * 2]);
    float2 fpp = unpk(*(const uint2*)&pc[(size_t)r * 64 + j * 2]);
    out[(size_t)r * 64 + 2 * j] = fh.x;
    out[(size_t)r * 64 + 2 * j + 1] = fh.y;
    out[(size_t)NN * 64 + (size_t)r * 64 + 2 * j] = fpp.x;
    out[(size_t)NN * 64 + (size_t)r * 64 + 2 * j + 1] = fpp.y;
}

__global__ void pack_inputs(const float* __restrict__ h_in, const float* __restrict__ p_in) {
    int idx = blockIdx.x * blockDim.x + threadIdx.x;
    if (idx < NN) g_deg[idx] = 0;
    if (idx < NN * 64) {
        int r = idx >> 6, j = idx & 63;
        float v0 = h_in[(size_t)r * 128 + 2 * j];
        float v1 = h_in[(size_t)r * 128 + 2 * j + 1];
        *(uint2*)&g_hin[((size_t)r * 64 + j) * 2] = pk(v0, v1);
    } else if (idx < NN * 64 + NN * 8) {
        int k = idx - NN * 64;
        int r = k >> 3, j = k & 7;
        float v0 = p_in[(size_t)r * 16 + 2 * j];
        float v1 = p_in[(size_t)r * 16 + 2 * j + 1];
        *(uint2*)&g_pin[((size_t)r * 8 + j) * 2] = pk(v0, v1);
    }
}

// slot 0: he_W (64 pairs), slot 1: pe_W (8 pairs); per layer i, base b=2+i*13:
// +0 Wm_hs +1 Wm_ps +2 Wm_hr +3 Wm_pr +4 Wm_e +5 We_hs +6 We_hr +7 We_e
// +8 Wp_ps +9 Wp_pr +10 Wp_e +11 huW(64 pairs) +12 puW(64 pairs)
__global__ void pack_weights(const float* __restrict__ heW, const float* __restrict__ peW,
                             const float* __restrict__ hmW, const float* __restrict__ euW,
                             const float* __restrict__ pmW, const float* __restrict__ huW,
                             const float* __restrict__ puW) {
    int m = blockIdx.x;
    const float* src; int Kw;
    if (m == 0) { src = heW; Kw = 64; }
    else if (m == 1) { src = peW; Kw = 8; }
    else {
        int mm = m - 2, i = mm / 13, j = mm % 13;
        if (j < 5)       { src = hmW + (size_t)i * 20480 + j * 4096; Kw = 32; }
        else if (j < 8)  { src = euW + (size_t)i * 12288 + (j - 5) * 4096; Kw = 32; }
        else if (j < 10) { src = pmW + (size_t)i * 12288 + (j - 8) * 4096; Kw = 32; }
        else if (j == 10){ src = pmW + (size_t)i * 12288 + 2 * 4096; Kw = 32; }
        else if (j == 11){ src = huW + (size_t)i * 8192; Kw = 64; }
        else             { src = puW + (size_t)i * 8192; Kw = 64; }
    }
    unsigned* dst = g_w + (size_t)m * 8192;
    for (int idx = threadIdx.x; idx < 64 * Kw; idx += blockDim.x) {
        int c = idx & 63, k2 = idx >> 6;
        float v0 = src[(size_t)(2 * k2) * 64 + c];
        float v1 = src[(size_t)(2 * k2 + 1) * 64 + c];
        *(uint2*)&dst[(size_t)(c * Kw + k2) * 2] = pk(v0, v1);
    }
}

// ---------------- weight composition ----------------
// type 0: Z[k1,64] = X@Y, pack to slot (wst pairs/col), optional fp32 copy to ws
// type 1: bout[64] = X[64]@Y + (X2?  X2[64]@Y2 : 0)
struct Job {
    const float* X; const float* Y;
    const float* X2; const float* Y2;
    unsigned* slot; float* ws; float* bout;
    int k1; int wst; int type;
};
struct Jobs { Job j[38]; };

__global__ __launch_bounds__(256) void compose_mats(Jobs ja) {
    Job jb = ja.j[blockIdx.x];
    __shared__ float sY[64 * 64];
    int t = threadIdx.x;
    if (jb.type == 0) {
        for (int i = t; i < 4096; i += 256) sY[i] = jb.Y[i];
        __syncthreads();
        int c = t & 63, mg = t >> 6;
        int kp = jb.k1 >> 1;
        for (int m = mg; m < kp; m += 4) {
            float z0 = 0.f, z1 = 0.f;
            const float* x0 = jb.X + (size_t)(2 * m) * 64;
            const float* x1 = x0 + 64;
            #pragma unroll 8
            for (int kk = 0; kk < 64; kk++) {
                float yv = sY[kk * 64 + c];
                z0 += x0[kk] * yv; z1 += x1[kk] * yv;
            }
            *(uint2*)&jb.slot[(size_t)(c * jb.wst + m) * 2] = pk(z0, z1);
            if (jb.ws) {
                jb.ws[(size_t)(2 * m) * 64 + c] = z0;
                jb.ws[(size_t)(2 * m + 1) * 64 + c] = z1;
            }
        }
    } else {
        if (t < 64) {
            float s = 0.f;
            for (int kk = 0; kk < 64; kk++) s += jb.X[kk] * jb.Y[kk * 64 + t];
            if (jb.X2)
                for (int kk = 0; kk < 64; kk++) s += jb.X2[kk] * jb.Y2[kk * 64 + t];
            jb.bout[t] = s;
        }
    }
}

// ---------------- CSR build ----------------
__global__ void deg_kernel(const int* __restrict__ rec) {
    int j = blockIdx.x * blockDim.x + threadIdx.x;
    if (j < EE) atomicAdd(&g_deg[rec[j]], 1);
}
__global__ __launch_bounds__(1024) void scan_kernel(int n) {
    __shared__ int wsum[32];
    __shared__ int carry;
    int t = threadIdx.x, lane = t & 31, wid = t >> 5;
    if (t == 0) { carry = 0; g_rowptr[0] = 0; g_cursor[0] = 0; }
    __syncthreads();
    for (int base = 0; base < n; base += 1024) {
        int i = base + t;
        int v = (i < n) ? g_deg[i] : 0;
        int x = v;
        #pragma unroll
        for (int o = 1; o < 32; o <<= 1) {
            int y = __shfl_up_sync(0xffffffffu, x, o);
            if (lane >= o) x += y;
        }
        if (lane == 31) wsum[wid] = x;
        __syncthreads();
        if (wid == 0) {
            int s = wsum[lane];
            #pragma unroll
            for (int o = 1; o < 32; o <<= 1) {
                int y = __shfl_up_sync(0xffffffffu, s, o);
                if (lane >= o) s += y;
            }
            wsum[lane] = s;
        }
        __syncthreads();
        int off = carry + (wid ? wsum[wid - 1] : 0);
        if (i < n) {
            g_rowptr[i + 1] = off + x;
            if (i + 1 < n) g_cursor[i + 1] = off + x;
        }
        __syncthreads();
        if (t == 0) carry += wsum[31];
        __syncthreads();
    }
}
__global__ void fill_kernel(const int* __restrict__ send, const int* __restrict__ rec) {
    int j = blockIdx.x * blockDim.x + threadIdx.x;
    if (j < EE) {
        int pos = atomicAdd(&g_cursor[rec[j]], 1);
        g_col[pos] = send[j];
        g_eid[pos] = j;
    }
}
__global__ __launch_bounds__(256) void esum_csr(const float* __restrict__ e_in) {
    int t = threadIdx.x;
    int node = blockIdx.x * 8 + (t >> 5);
    if (node >= NN) return;
    int lane = t & 31;
    int beg = g_rowptr[node], end = g_rowptr[node + 1];
    float v = 0.f;
    for (int e = beg + (lane >> 4); e < end; e += 2)
        v += e_in[(size_t)g_eid[e] * 16 + (lane & 15)];
    v += __shfl_down_sync(0xffffffffu, v, 16);
    if (lane < 16) g_esum[node * 16 + lane] = v;
}

// ---------------- precompute per-layer small matrices (EW/ec recurrence) ----------------
__global__ __launch_bounds__(1024) void precompute_small(
    const float* __restrict__ eeW, const float* __restrict__ eeb,
    const float* __restrict__ hmW, const float* __restrict__ hmb,
    const float* __restrict__ euW, const float* __restrict__ eub,
    const float* __restrict__ pmW, const float* __restrict__ pmb)
{
    __shared__ float sEW[1024], sec[64], sEW2[1024], sec2[64];
    int t = threadIdx.x;
    int r = t >> 6, c = t & 63;
    sEW[t] = eeW[t];
    if (t < 64) sec[t] = eeb[t];
    __syncthreads();
    for (int i = 0; i < LL; i++) {
        const float* Wm_e = hmW + (size_t)i * 320 * 64 + 256 * 64;
        const float* We_e = euW + (size_t)i * 192 * 64 + 128 * 64;
        const float* Wp_e = pmW + (size_t)i * 192 * 64 + 128 * 64;
        float s = 0.f;
        #pragma unroll 8
        for (int k = 0; k < 64; k++) s += sEW[r * 64 + k] * Wm_e[k * 64 + c];
        g_Gh[i * 1024 + t] = s;
        if (t < 64) {
            float s2 = hmb[i * 64 + t];
            for (int k = 0; k < 64; k++) s2 += sec[k] * Wm_e[k * 64 + t];
            g_ch[i * 64 + t] = s2;
        }
        s = 0.f;
        #pragma unroll 8
        for (int k = 0; k < 64; k++) s += sEW[r * 64 + k] * We_e[k * 64 + c];
        sEW2[t] = s;
        if (t < 64) {
            float s2 = eub[i * 64 + t];
            for (int k = 0; k < 64; k++) s2 += sec[k] * We_e[k * 64 + t];
            sec2[t] = s2;
        }
        __syncthreads();
        sEW[t] = sEW2[t];
        if (t < 64) sec[t] = sec2[t];
        __syncthreads();
        s = 0.f;
        #pragma unroll 8
        for (int k = 0; k < 64; k++) s += sEW[r * 64 + k] * Wp_e[k * 64 + c];
        g_Gp[i * 1024 + t] = s;
        if (t < 64) {
            float s2 = pmb[i * 64 + t];
            for (int k = 0; k < 64; k++) s2 += sec[k] * Wp_e[k * 64 + t];
            g_cp[i * 64 + t] = s2;
        }
        __syncthreads();
    }
}

// ---------------- multi-output streaming tensor-core GEMM ----------------
// grid (NP/128, ny); blockIdx.y = output index with its own term list.
struct GArgs {
    const unsigned* A[MAXY][MAXT];
    const unsigned* W[MAXY][MAXT];
    int Aw2[MAXY][MAXT];
    int Kst[MAXY][MAXT];
    int Wst[MAXY][MAXT];
    int nt[MAXY];
    unsigned* C[MAXY];
    const float* bias[MAXY];
};

__global__ __launch_bounds__(256) void stream_gemm(GArgs ga) {
    extern __shared__ unsigned sW[];
    int y = blockIdx.y;
    int t = threadIdx.x;
    int w = t >> 5, lane = t & 31;
    int wm = w >> 1, wn = w & 1;
    int gq = lane >> 2, q = lane & 3;
    int nt = ga.nt[y];

    int off = 0;
    for (int tm = 0; tm < nt; tm++) {
        const unsigned* Wg = ga.W[y][tm];
        int Tp = ga.Kst[y][tm] * 8;
        int cs = Tp * 2 + 2;
        int wst = ga.Wst[y][tm];
        for (int idx = t; idx < 64 * Tp; idx += 256) {
            int c = idx / Tp, pp = idx - c * Tp;
            uint2 v = *(const uint2*)&Wg[(size_t)(c * wst + pp) * 2];
            sW[off + c * cs + pp * 2] = v.x;
            sW[off + c * cs + pp * 2 + 1] = v.y;
        }
        off += 64 * cs;
    }
    __syncthreads();

    float acc[2][4][4];
    #pragma unroll
    for (int mt = 0; mt < 2; mt++)
        #pragma unroll
        for (int ntI = 0; ntI < 4; ntI++)
            #pragma unroll
            for (int i = 0; i < 4; i++) acc[mt][ntI][i] = 0.f;

    int rowb = blockIdx.x * 128 + wm * 32 + gq;

    off = 0;
    for (int tm = 0; tm < nt; tm++) {
        const unsigned* A = ga.A[y][tm];
        int aw2 = ga.Aw2[y][tm];
        int kst = ga.Kst[y][tm];
        int cs = kst * 16 + 2;
        const unsigned* wsm = sW + off;
        for (int ks = 0; ks < kst; ks++) {
            unsigned ah[2][4], al[2][4];
            #pragma unroll
            for (int mt = 0; mt < 2; mt++) {
                size_t rb0 = (size_t)(rowb + mt * 16) * aw2;
                size_t rb8 = (size_t)(rowb + mt * 16 + 8) * aw2;
                int p0 = (ks * 8 + q) * 2, p1 = (ks * 8 + q + 4) * 2;
                uint2 v0 = *(const uint2*)&A[rb0 + p0];
                uint2 v1 = *(const uint2*)&A[rb8 + p0];
                uint2 v2 = *(const uint2*)&A[rb0 + p1];
                uint2 v3 = *(const uint2*)&A[rb8 + p1];
                ah[mt][0] = v0.x; al[mt][0] = v0.y;
                ah[mt][1] = v1.x; al[mt][1] = v1.y;
                ah[mt][2] = v2.x; al[mt][2] = v2.y;
                ah[mt][3] = v3.x; al[mt][3] = v3.y;
            }
            #pragma unroll
            for (int ntI = 0; ntI < 4; ntI++) {
                int c = wn * 32 + ntI * 8 + gq;
                uint2 b0 = *(const uint2*)&wsm[c * cs + (ks * 8 + q) * 2];
                uint2 b1 = *(const uint2*)&wsm[c * cs + (ks * 8 + q + 4) * 2];
                unsigned bh[2] = {b0.x, b1.x};
                unsigned bl[2] = {b0.y, b1.y};
                #pragma unroll
                for (int mt = 0; mt < 2; mt++) {
                    mma_bf16(acc[mt][ntI], ah[mt], bh);
                    mma_bf16(acc[mt][ntI], ah[mt], bl);
                    mma_bf16(acc[mt][ntI], al[mt], bh);
                }
            }
        }
        off += 64 * cs;
    }

    unsigned* C = ga.C[y];
    const float* bias = ga.bias[y];
    #pragma unroll
    for (int ntI = 0; ntI < 4; ntI++) {
        int cb = wn * 32 + ntI * 8 + q * 2;
        float bx = bias ? bias[cb] : 0.f;
        float by = bias ? bias[cb + 1] : 0.f;
        #pragma unroll
        for (int mt = 0; mt < 2; mt++) {
            int row = blockIdx.x * 128 + wm * 32 + mt * 16 + gq;
            if (row < NN)
                *(uint2*)&C[(size_t)row * 64 + cb] =
                    pk(acc[mt][ntI][0] + bx, acc[mt][ntI][1] + by);
            if (row + 8 < NN)
                *(uint2*)&C[(size_t)(row + 8) * 64 + cb] =
                    pk(acc[mt][ntI][2] + bx, acc[mt][ntI][3] + by);
        }
    }
}

// ---------------- SpMM ----------------
__global__ __launch_bounds__(256) void spmm_kernel(
    unsigned* __restrict__ agg, const unsigned* __restrict__ S,
    const unsigned* __restrict__ R, int layer, int pbranch)
{
    __shared__ float sG[16 * 64];
    __shared__ float sc[64];
    int t = threadIdx.x;
    const float* G = (pbranch ? g_Gp : g_Gh) + layer * 1024;
    const float* cc = (pbranch ? g_cp : g_ch) + layer * 64;
    for (int i = t; i < 1024; i += 256) sG[i] = G[i];
    if (t < 64) sc[t] = cc[t];
    __syncthreads();
    int node = blockIdx.x * 8 + (t >> 5);
    if (node >= NN) return;
    int lane = t & 31;
    int beg = g_rowptr[node], end = g_rowptr[node + 1];
    float ax = 0.f, ay = 0.f;
    int e = beg;
    for (; e + 4 <= end; e += 4) {
        int u0 = g_col[e], u1 = g_col[e + 1], u2 = g_col[e + 2], u3 = g_col[e + 3];
        uint2 v0 = *(const uint2*)&S[(size_t)u0 * 64 + lane * 2];
        uint2 v1 = *(const uint2*)&S[(size_t)u1 * 64 + lane * 2];
        uint2 v2 = *(const uint2*)&S[(size_t)u2 * 64 + lane * 2];
        uint2 v3 = *(const uint2*)&S[(size_t)u3 * 64 + lane * 2];
        float2 f0 = unpk(v0), f1 = unpk(v1), f2 = unpk(v2), f3 = unpk(v3);
        ax += (f0.x + f1.x) + (f2.x + f3.x);
        ay += (f0.y + f1.y) + (f2.y + f3.y);
    }
    for (; e < end; e++) {
        int u = g_col[e];
        float2 f = unpk(*(const uint2*)&S[(size_t)u * 64 + lane * 2]);
        ax += f.x; ay += f.y;
    }
    float deg = (float)(end - beg);
    int c0 = lane * 2;
    float2 r2 = unpk(*(const uint2*)&R[(size_t)node * 64 + lane * 2]);
    float t0 = deg * (r2.x + sc[c0]) + ax;
    float t1 = deg * (r2.y + sc[c0 + 1]) + ay;
    #pragma unroll
    for (int k = 0; k < 16; k++) {
        float ev = g_esum[node * 16 + k];
        t0 += ev * sG[k * 64 + c0];
        t1 += ev * sG[k * 64 + c0 + 1];
    }
    *(uint2*)&agg[(size_t)node * 64 + lane * 2] = pk(t0, t1);
}

// ---------------- host ----------------
extern "C" void kernel_launch(void* const* d_in, const int* in_sizes, int n_in,
                              void* d_out, int out_size)
{
    const float* h_in = (const float*)d_in[0];
    const float* e_in = (const float*)d_in[1];
    const float* p_in = (const float*)d_in[2];
    const int*   ei   = (const int*)d_in[3];
    const int* send = ei;
    const int* rec  = ei + EE;
    const float* he_W = (const float*)d_in[4];
    const float* he_b = (const float*)d_in[5];
    const float* ee_W = (const float*)d_in[6];
    const float* ee_b = (const float*)d_in[7];
    const float* pe_W = (const float*)d_in[8];
    const float* pe_b = (const float*)d_in[9];
    const float* hm_W = (const float*)d_in[10];
    const float* hm_b = (const float*)d_in[11];
    const float* hu_W = (const float*)d_in[12];
    const float* hu_b = (const float*)d_in[13];
    const float* eu_W = (const float*)d_in[14];
    const float* eu_b = (const float*)d_in[15];
    const float* pm_W = (const float*)d_in[16];
    const float* pm_b = (const float*)d_in[17];
    const float* pu_W = (const float*)d_in[18];
    const float* pu_b = (const float*)d_in[19];

    static unsigned* base_h = nullptr;
    static unsigned *base_h2, *base_p, *base_p2, *base_EA, *base_EA2,
                    *base_EB, *base_EB2, *fS, *fR, *fagg, *fhin, *fpin, *fw;
    static float *fcw, *fbias;
    if (base_h == nullptr) {
        void* ptr;
        cudaGetSymbolAddress(&ptr, g_h);    base_h   = (unsigned*)ptr;
        cudaGetSymbolAddress(&ptr, g_h2);   base_h2  = (unsigned*)ptr;
        cudaGetSymbolAddress(&ptr, g_p);    base_p   = (unsigned*)ptr;
        cudaGetSymbolAddress(&ptr, g_p2);   base_p2  = (unsigned*)ptr;
        cudaGetSymbolAddress(&ptr, g_EA);   base_EA  = (unsigned*)ptr;
        cudaGetSymbolAddress(&ptr, g_EA2);  base_EA2 = (unsigned*)ptr;
        cudaGetSymbolAddress(&ptr, g_EB);   base_EB  = (unsigned*)ptr;
        cudaGetSymbolAddress(&ptr, g_EB2);  base_EB2 = (unsigned*)ptr;
        cudaGetSymbolAddress(&ptr, g_S);    fS   = (unsigned*)ptr;
        cudaGetSymbolAddress(&ptr, g_R);    fR   = (unsigned*)ptr;
        cudaGetSymbolAddress(&ptr, g_agg);  fagg = (unsigned*)ptr;
        cudaGetSymbolAddress(&ptr, g_hin);  fhin = (unsigned*)ptr;
        cudaGetSymbolAddress(&ptr, g_pin);  fpin = (unsigned*)ptr;
        cudaGetSymbolAddress(&ptr, g_w);    fw   = (unsigned*)ptr;
        cudaGetSymbolAddress(&ptr, g_cw);   fcw  = (float*)ptr;
        cudaGetSymbolAddress(&ptr, g_bias); fbias = (float*)ptr;
        cudaFuncSetAttribute(stream_gemm,
                             cudaFuncAttributeMaxDynamicSharedMemorySize, 72 * 1024);
    }
    #define WSLOT(s) (fw + (size_t)(s) * 8192)
    #define CW(n)    (fcw + (size_t)(n) * 4096)
    #define BIAS(n)  (fbias + (size_t)(n) * 64)

    // fp32 weight sub-block helpers
    auto Wm = [&](int i, int j){ return hm_W + (size_t)i * 320 * 64 + (size_t)j * 4096; };
    auto We = [&](int i, int j){ return eu_W + (size_t)i * 192 * 64 + (size_t)j * 4096; };
    auto Wp = [&](int i, int j){ return pm_W + (size_t)i * 192 * 64 + (size_t)j * 4096; };
    auto hu1 = [&](int i){ return hu_W + (size_t)i * 8192; };
    auto hu2 = [&](int i){ return hu_W + (size_t)i * 8192 + 4096; };
    auto pu1 = [&](int i){ return pu_W + (size_t)i * 8192; };
    auto pu2 = [&](int i){ return pu_W + (size_t)i * 8192 + 4096; };

    unsigned *hc = base_h, *hn = base_h2;
    unsigned *pc = base_p, *pn = base_p2;
    unsigned *EAc = base_EA, *EAn = base_EA2;
    unsigned *EBc = base_EB, *EBn = base_EB2;

    const int EB256 = (EE + 255) / 256;
    const int GB = NP / 128;
    const int SB = (NN + 7) / 8;

    // ---- compose job tables ----
    Jobs JA; memset(&JA, 0, sizeof(JA));
    int na = 0;
    auto matJ = [&](Jobs& J, int& n, const float* X, const float* Y,
                    int slot, float* ws, int k1, int wst) {
        J.j[n].X = X; J.j[n].Y = Y; J.j[n].slot = WSLOT(slot);
        J.j[n].ws = ws; J.j[n].k1 = k1; J.j[n].wst = wst; J.j[n].type = 0; n++;
    };
    auto biasJ = [&](Jobs& J, int& n, const float* X, const float* Y,
                     const float* X2, const float* Y2, float* bout) {
        J.j[n].X = X; J.j[n].Y = Y; J.j[n].X2 = X2; J.j[n].Y2 = Y2;
        J.j[n].bout = bout; J.j[n].type = 1; n++;
    };
    for (int i = 0; i < LL; i++) {
        int nb = 54 + i * 13;
        matJ(JA, na, hu1(i), We(i, 0), nb + 0, CW(i * 4 + 0), 64, 32);
        matJ(JA, na, hu2(i), We(i, 0), nb + 1, CW(i * 4 + 1), 64, 32);
        matJ(JA, na, hu1(i), We(i, 1), nb + 2, CW(i * 4 + 2), 64, 32);
        matJ(JA, na, hu2(i), We(i, 1), nb + 3, CW(i * 4 + 3), 64, 32);
        matJ(JA, na, We(i, 2), Wp(i, 2), nb + 4, nullptr, 64, 32);
        if (i < 3) {
            matJ(JA, na, pu1(i), Wm(i + 1, 1), nb + 9,  nullptr, 64, 32);
            matJ(JA, na, pu2(i), Wm(i + 1, 1), nb + 10, nullptr, 64, 32);
            matJ(JA, na, pu1(i), Wm(i + 1, 3), nb + 11, nullptr, 64, 32);
            matJ(JA, na, pu2(i), Wm(i + 1, 3), nb + 12, nullptr, 64, 32);
        }
    }
    matJ(JA, na, he_W, Wm(0, 0), 106, nullptr, 128, 64);
    matJ(JA, na, he_W, Wm(0, 2), 107, nullptr, 128, 64);
    matJ(JA, na, pe_W, Wm(0, 1), 108, nullptr, 16, 8);
    matJ(JA, na, pe_W, Wm(0, 3), 109, nullptr, 16, 8);
    biasJ(JA, na, he_b, Wm(0, 0), pe_b, Wm(0, 1), BIAS(24));
    biasJ(JA, na, he_b, Wm(0, 2), pe_b, Wm(0, 3), BIAS(25));  // na = 38

    Jobs JAb; memset(&JAb, 0, sizeof(JAb));
    int nab = 0;
    for (int i = 0; i < LL; i++) {
        biasJ(JAb, nab, hu_b + i * 64, We(i, 0), nullptr, nullptr, BIAS(6 * i + 0));
        biasJ(JAb, nab, hu_b + i * 64, We(i, 1), nullptr, nullptr, BIAS(6 * i + 1));
        if (i < 3) {
            biasJ(JAb, nab, pu_b + i * 64, Wm(i + 1, 1), nullptr, nullptr, BIAS(6 * i + 4));
            biasJ(JAb, nab, pu_b + i * 64, Wm(i + 1, 3), nullptr, nullptr, BIAS(6 * i + 5));
        }
    }

    Jobs JB; memset(&JB, 0, sizeof(JB));
    int nbj = 0;
    for (int i = 0; i < LL; i++) {
        int nb = 54 + i * 13;
        matJ(JB, nbj, CW(i * 4 + 0), Wp(i, 2), nb + 5, nullptr, 64, 32);
        matJ(JB, nbj, CW(i * 4 + 1), Wp(i, 2), nb + 6, nullptr, 64, 32);
        matJ(JB, nbj, CW(i * 4 + 2), Wp(i, 2), nb + 7, nullptr, 64, 32);
        matJ(JB, nbj, CW(i * 4 + 3), Wp(i, 2), nb + 8, nullptr, 64, 32);
        biasJ(JB, nbj, BIAS(6 * i + 0), Wp(i, 2), nullptr, nullptr, BIAS(6 * i + 2));
        biasJ(JB, nbj, BIAS(6 * i + 1), Wp(i, 2), nullptr, nullptr, BIAS(6 * i + 3));
    }

    // ---- GArgs helpers ----
    GArgs ga;
    auto clearG = [&]() { memset(&ga, 0, sizeof(ga)); };
    auto setY = [&](int y, unsigned* C, const float* bias) {
        ga.C[y] = C; ga.bias[y] = bias; ga.nt[y] = 0;
    };
    auto addT = [&](int y, const unsigned* A, int Aw2, int Kst, unsigned* W, int Wst) {
        int tt = ga.nt[y];
        ga.A[y][tt] = A; ga.Aw2[y][tt] = Aw2; ga.Kst[y][tt] = Kst;
        ga.W[y][tt] = W; ga.Wst[y][tt] = Wst; ga.nt[y] = tt + 1;
    };
    auto smemB = [&](int ny) {
        int mx = 0;
        for (int y = 0; y < ny; y++) {
            int s = 0;
            for (int tt = 0; tt < ga.nt[y]; tt++) s += 64 * (ga.Kst[y][tt] * 16 + 2);
            if (s > mx) mx = s;
        }
        return (size_t)mx * 4;
    };

    // ================= launches =================
    pack_weights<<<54, 256>>>(he_W, pe_W, hm_W, eu_W, pm_W, hu_W, pu_W);   // 0
    pack_inputs<<<(NN * 72 + 255) / 256, 256>>>(h_in, p_in);               // 1
    compose_mats<<<na, 256>>>(JA);                                         // 2

    // ---- prologue: [h0, p0, S_h0, R_h0]  (launch index 3 → profiled) ----
    clearG();
    setY(0, hc, he_b);          addT(0, fhin, 128, 8, WSLOT(0), 64);
    setY(1, pc, pe_b);          addT(1, fpin, 16, 1, WSLOT(1), 8);
    setY(2, fS, BIAS(24));      addT(2, fhin, 128, 8, WSLOT(106), 64);
                                addT(2, fpin, 16, 1, WSLOT(108), 8);
    setY(3, fR, BIAS(25));      addT(3, fhin, 128, 8, WSLOT(107), 64);
                                addT(3, fpin, 16, 1, WSLOT(109), 8);
    stream_gemm<<<dim3(GB, 4), 256, smemB(4)>>>(ga);                       // 3

    compose_mats<<<nab, 256>>>(JAb);                                       // 4
    compose_mats<<<nbj, 256>>>(JB);                                        // 5
    precompute_small<<<1, 1024>>>(ee_W, ee_b, hm_W, hm_b, eu_W, eu_b, pm_W, pm_b); // 6
    deg_kernel<<<EB256, 256>>>(rec);                                       // 7
    scan_kernel<<<1, 1024>>>(NN);                                          // 8
    fill_kernel<<<EB256, 256>>>(send, rec);                                // 9
    esum_csr<<<SB, 256>>>(e_in);                                           // 10

    // ================= layers =================
    for (int i = 0; i < LL; i++) {
        int b = 2 + i * 13;
        int nb = 54 + i * 13;

        spmm_kernel<<<SB, 256>>>(fagg, fS, fR, i, 0);

        // G1: [h', EA', EB', S_p, R_p]
        clearG();
        setY(0, hn, hu_b + i * 64);
        addT(0, hc, 64, 4, WSLOT(b + 11), 64);
        addT(0, fagg, 64, 4, WSLOT(b + 11) + 64, 64);
        setY(1, EAn, BIAS(6 * i + 0));
        addT(1, hc, 64, 4, WSLOT(nb + 0), 32);
        addT(1, fagg, 64, 4, WSLOT(nb + 1), 32);
        if (i > 0) addT(1, EAc, 64, 4, WSLOT(b + 7), 32);
        setY(2, EBn, BIAS(6 * i + 1));
        addT(2, hc, 64, 4, WSLOT(nb + 2), 32);
        addT(2, fagg, 64, 4, WSLOT(nb + 3), 32);
        if (i > 0) addT(2, EBc, 64, 4, WSLOT(b + 7), 32);
        setY(3, fS, BIAS(6 * i + 2));
        addT(3, pc, 64, 4, WSLOT(b + 8), 32);
        addT(3, hc, 64, 4, WSLOT(nb + 5), 32);
        addT(3, fagg, 64, 4, WSLOT(nb + 6), 32);
        if (i > 0) addT(3, EAc, 64, 4, WSLOT(nb + 4), 32);
        setY(4, fR, BIAS(6 * i + 3));
        addT(4, pc, 64, 4, WSLOT(b + 9), 32);
        addT(4, hc, 64, 4, WSLOT(nb + 7), 32);
        addT(4, fagg, 64, 4, WSLOT(nb + 8), 32);
        if (i > 0) addT(4, EBc, 64, 4, WSLOT(nb + 4), 32);
        stream_gemm<<<dim3(GB, 5), 256, smemB(5)>>>(ga);
        { unsigned* t1 = hc; hc = hn; hn = t1; }
        { unsigned* t1 = EAc; EAc = EAn; EAn = t1; }
        { unsigned* t1 = EBc; EBc = EBn; EBn = t1; }

        spmm_kernel<<<SB, 256>>>(fagg, fS, fR, i, 1);

        // G2: [p'] (+ next layer's [S_h, R_h] if i<3)
        clearG();
        setY(0, pn, pu_b + i * 64);
        addT(0, pc, 64, 4, WSLOT(b + 12), 64);
        addT(0, fagg, 64, 4, WSLOT(b + 12) + 64, 64);
        int ny = 1;
        if (i < 3) {
            int bj = 2 + (i + 1) * 13;
            setY(1, fS, BIAS(6 * i + 4));
            addT(1, hc, 64, 4, WSLOT(bj + 0), 32);
            addT(1, EAc, 64, 4, WSLOT(bj + 4), 32);
            addT(1, pc, 64, 4, WSLOT(nb + 9), 32);
            addT(1, fagg, 64, 4, WSLOT(nb + 10), 32);
            setY(2, fR, BIAS(6 * i + 5));
            addT(2, hc, 64, 4, WSLOT(bj + 2), 32);
            addT(2, EBc, 64, 4, WSLOT(bj + 4), 32);
            addT(2, pc, 64, 4, WSLOT(nb + 11), 32);
            addT(2, fagg, 64, 4, WSLOT(nb + 12), 32);
            ny = 3;
        }
        stream_gemm<<<dim3(GB, ny), 256, smemB(ny)>>>(ga);
        { unsigned* t1 = pc; pc = pn; pn = t1; }
    }

    // ----- output -----
    out_kernel<<<(NN * 32 + 255) / 256, 256>>>((float*)d_out, hc, pc);
}

// round 12
// speedup vs baseline: 1.0022x; 1.0022x over previous
#include <cuda_runtime.h>
#include <cuda_bf16.h>

#define NN 50000
#define NP 50048
#define EE 800000
#define LL 4
#define MAXY 4
#define MAXT 4

// ---------------- storage ----------------
// col-major (pair-major) packed arrays: uint2 at (pair*NP + row)
__device__ unsigned g_h[NP * 64];
__device__ unsigned g_h2[NP * 64];
__device__ unsigned g_p[NP * 64];
__device__ unsigned g_p2[NP * 64];
__device__ unsigned g_EA[NP * 64];
__device__ unsigned g_EA2[NP * 64];
__device__ unsigned g_EB[NP * 64];
__device__ unsigned g_EB2[NP * 64];
__device__ unsigned g_agg[NP * 64];
__device__ unsigned g_hin[NP * 128];
__device__ unsigned g_pin[NP * 16];
// fp32 row-major (GEMM out -> spmm in)
__device__ float g_S[NP * 64];
__device__ float g_R[NP * 64];
__device__ unsigned g_w[110 * 8192];
__device__ float g_bias[26 * 64];
__device__ float g_esum[NN * 16];
__device__ int   g_deg[NN];
__device__ int   g_rowptr[NN + 1];
__device__ int   g_cursor[NN];
__device__ int   g_col[EE];
__device__ int   g_eid[EE];
__device__ float g_Gh[LL * 16 * 64];
__device__ float g_ch[LL * 64];
__device__ float g_Gp[LL * 16 * 64];
__device__ float g_cp[LL * 64];

// ---------------- helpers ----------------
__device__ __forceinline__ float2 unpk(uint2 v) {
    __nv_bfloat162 h = *(__nv_bfloat162*)&v.x;
    __nv_bfloat162 l = *(__nv_bfloat162*)&v.y;
    return make_float2(__bfloat162float(h.x) + __bfloat162float(l.x),
                       __bfloat162float(h.y) + __bfloat162float(l.y));
}
__device__ __forceinline__ uint2 pk(float a, float b) {
    __nv_bfloat162 hw = __floats2bfloat162_rn(a, b);
    float la = a - __bfloat162float(hw.x), lb = b - __bfloat162float(hw.y);
    __nv_bfloat162 lw = __floats2bfloat162_rn(la, lb);
    uint2 r; r.x = *(unsigned*)&hw; r.y = *(unsigned*)&lw; return r;
}
__device__ __forceinline__ void mma_bf16(float* d, const unsigned* a, const unsigned* b) {
    asm volatile(
        "mma.sync.aligned.m16n8k16.row.col.f32.bf16.bf16.f32 "
        "{%0,%1,%2,%3}, {%4,%5,%6,%7}, {%8,%9}, {%0,%1,%2,%3};"
        : "+f"(d[0]), "+f"(d[1]), "+f"(d[2]), "+f"(d[3])
        : "r"(a[0]), "r"(a[1]), "r"(a[2]), "r"(a[3]), "r"(b[0]), "r"(b[1]));
}

// ---------------- setup kernels ----------------
// transpose cm packed -> row-major fp32 out
__global__ __launch_bounds__(256) void out_kernel(float* __restrict__ out,
                                                  const unsigned* __restrict__ hc,
                                                  const unsigned* __restrict__ pc) {
    __shared__ float sh[64][66];
    __shared__ float sp[64][66];
    int r0 = blockIdx.x * 64;
    int t = threadIdx.x;
    #pragma unroll
    for (int it = 0; it < 8; it++) {
        int idx = t + it * 256;           // 2048 = 64 rows x 32 pairs
        int rr = idx & 63, j = idx >> 6;
        float2 fh = unpk(*(const uint2*)&hc[((size_t)j * NP + r0 + rr) * 2]);
        float2 fp2 = unpk(*(const uint2*)&pc[((size_t)j * NP + r0 + rr) * 2]);
        sh[rr][2 * j] = fh.x; sh[rr][2 * j + 1] = fh.y;
        sp[rr][2 * j] = fp2.x; sp[rr][2 * j + 1] = fp2.y;
    }
    __syncthreads();
    #pragma unroll
    for (int it = 0; it < 16; it++) {
        int idx = t + it * 256;           // 4096 = 64 rows x 64 cols
        int c = idx & 63, rr = idx >> 6;
        int row = r0 + rr;
        if (row < NN) {
            out[(size_t)row * 64 + c] = sh[rr][c];
            out[(size_t)NN * 64 + (size_t)row * 64 + c] = sp[rr][c];
        }
    }
}

__global__ void pack_inputs(const float* __restrict__ h_in, const float* __restrict__ p_in) {
    int idx = blockIdx.x * blockDim.x + threadIdx.x;
    if (idx < NN) g_deg[idx] = 0;
    if (idx < NN * 64) {
        int pr = idx / NN, r = idx - pr * NN;     // pair, row
        float v0 = h_in[(size_t)r * 128 + 2 * pr];
        float v1 = h_in[(size_t)r * 128 + 2 * pr + 1];
        *(uint2*)&g_hin[((size_t)pr * NP + r) * 2] = pk(v0, v1);
    } else if (idx < NN * 64 + NN * 8) {
        int k = idx - NN * 64;
        int pr = k / NN, r = k - pr * NN;
        float v0 = p_in[(size_t)r * 16 + 2 * pr];
        float v1 = p_in[(size_t)r * 16 + 2 * pr + 1];
        *(uint2*)&g_pin[((size_t)pr * NP + r) * 2] = pk(v0, v1);
    }
}

// weight slots (col-major packed):
// slot 0: he_W, 1: pe_W; per layer i, b=2+i*13:
// +0 Wm_hs +1 Wm_ps +2 Wm_hr +3 Wm_pr +4 Wm_e +5 We_hs +6 We_hr +7 We_e
// +8 Wp_ps +9 Wp_pr +10 Wp_e +11 huW +12 puW
__global__ void pack_weights(const float* __restrict__ heW, const float* __restrict__ peW,
                             const float* __restrict__ hmW, const float* __restrict__ euW,
                             const float* __restrict__ pmW, const float* __restrict__ huW,
                             const float* __restrict__ puW) {
    int m = blockIdx.x;
    const float* src; int Kw;
    if (m == 0) { src = heW; Kw = 64; }
    else if (m == 1) { src = peW; Kw = 8; }
    else {
        int mm = m - 2, i = mm / 13, j = mm % 13;
        if (j < 5)       { src = hmW + (size_t)i * 20480 + j * 4096; Kw = 32; }
        else if (j < 8)  { src = euW + (size_t)i * 12288 + (j - 5) * 4096; Kw = 32; }
        else if (j < 10) { src = pmW + (size_t)i * 12288 + (j - 8) * 4096; Kw = 32; }
        else if (j == 10){ src = pmW + (size_t)i * 12288 + 2 * 4096; Kw = 32; }
        else if (j == 11){ src = huW + (size_t)i * 8192; Kw = 64; }
        else             { src = puW + (size_t)i * 8192; Kw = 64; }
    }
    unsigned* dst = g_w + (size_t)m * 8192;
    for (int idx = threadIdx.x; idx < 64 * Kw; idx += blockDim.x) {
        int c = idx & 63, k2 = idx >> 6;
        float v0 = src[(size_t)(2 * k2) * 64 + c];
        float v1 = src[(size_t)(2 * k2 + 1) * 64 + c];
        *(uint2*)&dst[(size_t)(c * Kw + k2) * 2] = pk(v0, v1);
    }
}

// ---------------- weight composition ----------------
struct Job {
    const float* X; const float* Y;
    const float* X2; const float* Y2;
    unsigned* slot; float* bout;
    int k1; int wst; int type;
};
struct Jobs { Job j[48]; };

__global__ __launch_bounds__(256) void compose_mats(Jobs ja) {
    Job jb = ja.j[blockIdx.x];
    __shared__ float sY[64 * 64];
    int t = threadIdx.x;
    if (jb.type == 0) {
        for (int i = t; i < 4096; i += 256) sY[i] = jb.Y[i];
        __syncthreads();
        int c = t & 63, mg = t >> 6;
        int kp = jb.k1 >> 1;
        for (int m = mg; m < kp; m += 4) {
            float z0 = 0.f, z1 = 0.f;
            const float* x0 = jb.X + (size_t)(2 * m) * 64;
            const float* x1 = x0 + 64;
            #pragma unroll 8
            for (int kk = 0; kk < 64; kk++) {
                float yv = sY[kk * 64 + c];
                z0 += x0[kk] * yv; z1 += x1[kk] * yv;
            }
            *(uint2*)&jb.slot[(size_t)(c * jb.wst + m) * 2] = pk(z0, z1);
        }
    } else {
        if (t < 64) {
            float s = 0.f;
            for (int kk = 0; kk < 64; kk++) s += jb.X[kk] * jb.Y[kk * 64 + t];
            if (jb.X2)
                for (int kk = 0; kk < 64; kk++) s += jb.X2[kk] * jb.Y2[kk * 64 + t];
            jb.bout[t] = s;
        }
    }
}

// ---------------- CSR build ----------------
__global__ void deg_kernel(const int* __restrict__ rec) {
    int j = blockIdx.x * blockDim.x + threadIdx.x;
    if (j < EE) atomicAdd(&g_deg[rec[j]], 1);
}
__global__ __launch_bounds__(1024) void scan_kernel(int n) {
    __shared__ int wsum[32];
    __shared__ int carry;
    int t = threadIdx.x, lane = t & 31, wid = t >> 5;
    if (t == 0) { carry = 0; g_rowptr[0] = 0; g_cursor[0] = 0; }
    __syncthreads();
    for (int base = 0; base < n; base += 1024) {
        int i = base + t;
        int v = (i < n) ? g_deg[i] : 0;
        int x = v;
        #pragma unroll
        for (int o = 1; o < 32; o <<= 1) {
            int y = __shfl_up_sync(0xffffffffu, x, o);
            if (lane >= o) x += y;
        }
        if (lane == 31) wsum[wid] = x;
        __syncthreads();
        if (wid == 0) {
            int s = wsum[lane];
            #pragma unroll
            for (int o = 1; o < 32; o <<= 1) {
                int y = __shfl_up_sync(0xffffffffu, s, o);
                if (lane >= o) s += y;
            }
            wsum[lane] = s;
        }
        __syncthreads();
        int off = carry + (wid ? wsum[wid - 1] : 0);
        if (i < n) {
            g_rowptr[i + 1] = off + x;
            if (i + 1 < n) g_cursor[i + 1] = off + x;
        }
        __syncthreads();
        if (t == 0) carry += wsum[31];
        __syncthreads();
    }
}
__global__ void fill_kernel(const int* __restrict__ send, const int* __restrict__ rec) {
    int j = blockIdx.x * blockDim.x + threadIdx.x;
    if (j < EE) {
        int pos = atomicAdd(&g_cursor[rec[j]], 1);
        g_col[pos] = send[j];
        g_eid[pos] = j;
    }
}
__global__ __launch_bounds__(256) void esum_csr(const float* __restrict__ e_in) {
    int t = threadIdx.x;
    int node = blockIdx.x * 8 + (t >> 5);
    if (node >= NN) return;
    int lane = t & 31;
    int beg = g_rowptr[node], end = g_rowptr[node + 1];
    float v = 0.f;
    for (int e = beg + (lane >> 4); e < end; e += 2)
        v += e_in[(size_t)g_eid[e] * 16 + (lane & 15)];
    v += __shfl_down_sync(0xffffffffu, v, 16);
    if (lane < 16) g_esum[node * 16 + lane] = v;
}

// ---------------- precompute per-layer small matrices ----------------
__global__ __launch_bounds__(1024) void precompute_small(
    const float* __restrict__ eeW, const float* __restrict__ eeb,
    const float* __restrict__ hmW, const float* __restrict__ hmb,
    const float* __restrict__ euW, const float* __restrict__ eub,
    const float* __restrict__ pmW, const float* __restrict__ pmb)
{
    __shared__ float sEW[1024], sec[64], sEW2[1024], sec2[64];
    int t = threadIdx.x;
    int r = t >> 6, c = t & 63;
    sEW[t] = eeW[t];
    if (t < 64) sec[t] = eeb[t];
    __syncthreads();
    for (int i = 0; i < LL; i++) {
        const float* Wm_e = hmW + (size_t)i * 320 * 64 + 256 * 64;
        const float* We_e = euW + (size_t)i * 192 * 64 + 128 * 64;
        const float* Wp_e = pmW + (size_t)i * 192 * 64 + 128 * 64;
        float s = 0.f;
        #pragma unroll 8
        for (int k = 0; k < 64; k++) s += sEW[r * 64 + k] * Wm_e[k * 64 + c];
        g_Gh[i * 1024 + t] = s;
        if (t < 64) {
            float s2 = hmb[i * 64 + t];
            for (int k = 0; k < 64; k++) s2 += sec[k] * Wm_e[k * 64 + t];
            g_ch[i * 64 + t] = s2;
        }
        s = 0.f;
        #pragma unroll 8
        for (int k = 0; k < 64; k++) s += sEW[r * 64 + k] * We_e[k * 64 + c];
        sEW2[t] = s;
        if (t < 64) {
            float s2 = eub[i * 64 + t];
            for (int k = 0; k < 64; k++) s2 += sec[k] * We_e[k * 64 + t];
            sec2[t] = s2;
        }
        __syncthreads();
        sEW[t] = sEW2[t];
        if (t < 64) sec[t] = sec2[t];
        __syncthreads();
        s = 0.f;
        #pragma unroll 8
        for (int k = 0; k < 64; k++) s += sEW[r * 64 + k] * Wp_e[k * 64 + c];
        g_Gp[i * 1024 + t] = s;
        if (t < 64) {
            float s2 = pmb[i * 64 + t];
            for (int k = 0; k < 64; k++) s2 += sec[k] * Wp_e[k * 64 + t];
            g_cp[i * 64 + t] = s2;
        }
        __syncthreads();
    }
}

// ---------------- multi-output streaming tensor-core GEMM ----------------
// A arrays are col-major packed: uint2 at (pair*NP + row).
// Outputs: rmout ? fp32 row-major : packed col-major.
struct GArgs {
    const unsigned* A[MAXY][MAXT];
    const unsigned* W[MAXY][MAXT];
    int Kst[MAXY][MAXT];
    int Wst[MAXY][MAXT];
    int nt[MAXY];
    unsigned* C[MAXY];
    const float* bias[MAXY];
    int rmout[MAXY];
};

__global__ __launch_bounds__(256) void stream_gemm(GArgs ga) {
    extern __shared__ unsigned sW[];
    int y = blockIdx.y;
    int t = threadIdx.x;
    int w = t >> 5, lane = t & 31;
    int wm = w >> 1, wn = w & 1;
    int gq = lane >> 2, q = lane & 3;
    int nt = ga.nt[y];

    int off = 0;
    for (int tm = 0; tm < nt; tm++) {
        const unsigned* Wg = ga.W[y][tm];
        int Tp = ga.Kst[y][tm] * 8;
        int cs = Tp * 2 + 2;
        int wst = ga.Wst[y][tm];
        for (int idx = t; idx < 64 * Tp; idx += 256) {
            int c = idx / Tp, pp = idx - c * Tp;
            uint2 v = *(const uint2*)&Wg[(size_t)(c * wst + pp) * 2];
            sW[off + c * cs + pp * 2] = v.x;
            sW[off + c * cs + pp * 2 + 1] = v.y;
        }
        off += 64 * cs;
    }
    __syncthreads();

    float acc[2][4][4];
    #pragma unroll
    for (int mt = 0; mt < 2; mt++)
        #pragma unroll
        for (int ntI = 0; ntI < 4; ntI++)
            #pragma unroll
            for (int i = 0; i < 4; i++) acc[mt][ntI][i] = 0.f;

    int rowb = blockIdx.x * 128 + wm * 32 + gq;

    off = 0;
    for (int tm = 0; tm < nt; tm++) {
        const unsigned* A = ga.A[y][tm];
        int kst = ga.Kst[y][tm];
        int cs = kst * 16 + 2;
        const unsigned* wsm = sW + off;
        for (int ks = 0; ks < kst; ks++) {
            int pb = ks * 8 + q;
            unsigned ah[2][4], al[2][4];
            #pragma unroll
            for (int mt = 0; mt < 2; mt++) {
                int r = rowb + mt * 16;
                uint2 v0 = *(const uint2*)&A[((size_t)pb * NP + r) * 2];
                uint2 v1 = *(const uint2*)&A[((size_t)pb * NP + r + 8) * 2];
                uint2 v2 = *(const uint2*)&A[((size_t)(pb + 4) * NP + r) * 2];
                uint2 v3 = *(const uint2*)&A[((size_t)(pb + 4) * NP + r + 8) * 2];
                ah[mt][0] = v0.x; al[mt][0] = v0.y;
                ah[mt][1] = v1.x; al[mt][1] = v1.y;
                ah[mt][2] = v2.x; al[mt][2] = v2.y;
                ah[mt][3] = v3.x; al[mt][3] = v3.y;
            }
            #pragma unroll
            for (int ntI = 0; ntI < 4; ntI++) {
                int c = wn * 32 + ntI * 8 + gq;
                uint2 b0 = *(const uint2*)&wsm[c * cs + (ks * 8 + q) * 2];
                uint2 b1 = *(const uint2*)&wsm[c * cs + (ks * 8 + q + 4) * 2];
                unsigned bh[2] = {b0.x, b1.x};
                unsigned bl[2] = {b0.y, b1.y};
                #pragma unroll
                for (int mt = 0; mt < 2; mt++) {
                    mma_bf16(acc[mt][ntI], ah[mt], bh);
                    mma_bf16(acc[mt][ntI], ah[mt], bl);
                    mma_bf16(acc[mt][ntI], al[mt], bh);
                }
            }
        }
        off += 64 * cs;
    }

    unsigned* C = ga.C[y];
    const float* bias = ga.bias[y];
    int rm = ga.rmout[y];
    #pragma unroll
    for (int ntI = 0; ntI < 4; ntI++) {
        int cb = wn * 32 + ntI * 8 + q * 2;
        float bx = bias ? bias[cb] : 0.f;
        float by = bias ? bias[cb + 1] : 0.f;
        #pragma unroll
        for (int mt = 0; mt < 2; mt++) {
            int row = blockIdx.x * 128 + wm * 32 + mt * 16 + gq;
            float a0 = acc[mt][ntI][0] + bx, a1 = acc[mt][ntI][1] + by;
            float a2 = acc[mt][ntI][2] + bx, a3 = acc[mt][ntI][3] + by;
            if (rm) {
                float* Cf = (float*)C;
                if (row < NN)
                    *(float2*)&Cf[(size_t)row * 64 + cb] = make_float2(a0, a1);
                if (row + 8 < NN)
                    *(float2*)&Cf[(size_t)(row + 8) * 64 + cb] = make_float2(a2, a3);
            } else {
                size_t pbase = (size_t)(cb >> 1) * NP;
                if (row < NN)
                    *(uint2*)&C[(pbase + row) * 2] = pk(a0, a1);
                if (row + 8 < NN)
                    *(uint2*)&C[(pbase + row + 8) * 2] = pk(a2, a3);
            }
        }
    }
}

// ---------------- SpMM: fp32 S/R in (row-major), packed col-major agg out ----------------
__global__ __launch_bounds__(256) void spmm_kernel(
    unsigned* __restrict__ agg, const float* __restrict__ S,
    const float* __restrict__ R, int layer, int pbranch)
{
    __shared__ float sG[16 * 64];
    __shared__ float sc[64];
    int t = threadIdx.x;
    const float* G = (pbranch ? g_Gp : g_Gh) + layer * 1024;
    const float* cc = (pbranch ? g_cp : g_ch) + layer * 64;
    for (int i = t; i < 1024; i += 256) sG[i] = G[i];
    if (t < 64) sc[t] = cc[t];
    __syncthreads();
    int node = blockIdx.x * 8 + (t >> 5);
    if (node >= NN) return;
    int lane = t & 31;
    int beg = g_rowptr[node], end = g_rowptr[node + 1];
    const float2* S2 = (const float2*)S;
    float ax = 0.f, ay = 0.f;
    int e = beg;
    for (; e + 4 <= end; e += 4) {
        int u0 = g_col[e], u1 = g_col[e + 1], u2 = g_col[e + 2], u3 = g_col[e + 3];
        float2 f0 = S2[(size_t)u0 * 32 + lane];
        float2 f1 = S2[(size_t)u1 * 32 + lane];
        float2 f2 = S2[(size_t)u2 * 32 + lane];
        float2 f3 = S2[(size_t)u3 * 32 + lane];
        ax += (f0.x + f1.x) + (f2.x + f3.x);
        ay += (f0.y + f1.y) + (f2.y + f3.y);
    }
    for (; e < end; e++) {
        float2 f = S2[(size_t)g_col[e] * 32 + lane];
        ax += f.x; ay += f.y;
    }
    float deg = (float)(end - beg);
    int c0 = lane * 2;
    float2 r2 = ((const float2*)R)[(size_t)node * 32 + lane];
    float t0 = deg * (r2.x + sc[c0]) + ax;
    float t1 = deg * (r2.y + sc[c0 + 1]) + ay;
    #pragma unroll
    for (int k = 0; k < 16; k++) {
        float ev = g_esum[node * 16 + k];
        t0 += ev * sG[k * 64 + c0];
        t1 += ev * sG[k * 64 + c0 + 1];
    }
    *(uint2*)&agg[((size_t)lane * NP + node) * 2] = pk(t0, t1);
}

// ---------------- host ----------------
extern "C" void kernel_launch(void* const* d_in, const int* in_sizes, int n_in,
                              void* d_out, int out_size)
{
    const float* h_in = (const float*)d_in[0];
    const float* e_in = (const float*)d_in[1];
    const float* p_in = (const float*)d_in[2];
    const int*   ei   = (const int*)d_in[3];
    const int* send = ei;
    const int* rec  = ei + EE;
    const float* he_W = (const float*)d_in[4];
    const float* he_b = (const float*)d_in[5];
    const float* ee_W = (const float*)d_in[6];
    const float* ee_b = (const float*)d_in[7];
    const float* pe_W = (const float*)d_in[8];
    const float* pe_b = (const float*)d_in[9];
    const float* hm_W = (const float*)d_in[10];
    const float* hm_b = (const float*)d_in[11];
    const float* hu_W = (const float*)d_in[12];
    const float* hu_b = (const float*)d_in[13];
    const float* eu_W = (const float*)d_in[14];
    const float* eu_b = (const float*)d_in[15];
    const float* pm_W = (const float*)d_in[16];
    const float* pm_b = (const float*)d_in[17];
    const float* pu_W = (const float*)d_in[18];
    const float* pu_b = (const float*)d_in[19];

    static unsigned* base_h = nullptr;
    static unsigned *base_h2, *base_p, *base_p2, *base_EA, *base_EA2,
                    *base_EB, *base_EB2, *fagg, *fhin, *fpin, *fw;
    static float *fS, *fR, *fbias;
    if (base_h == nullptr) {
        void* ptr;
        cudaGetSymbolAddress(&ptr, g_h);    base_h   = (unsigned*)ptr;
        cudaGetSymbolAddress(&ptr, g_h2);   base_h2  = (unsigned*)ptr;
        cudaGetSymbolAddress(&ptr, g_p);    base_p   = (unsigned*)ptr;
        cudaGetSymbolAddress(&ptr, g_p2);   base_p2  = (unsigned*)ptr;
        cudaGetSymbolAddress(&ptr, g_EA);   base_EA  = (unsigned*)ptr;
        cudaGetSymbolAddress(&ptr, g_EA2);  base_EA2 = (unsigned*)ptr;
        cudaGetSymbolAddress(&ptr, g_EB);   base_EB  = (unsigned*)ptr;
        cudaGetSymbolAddress(&ptr, g_EB2);  base_EB2 = (unsigned*)ptr;
        cudaGetSymbolAddress(&ptr, g_S);    fS   = (float*)ptr;
        cudaGetSymbolAddress(&ptr, g_R);    fR   = (float*)ptr;
        cudaGetSymbolAddress(&ptr, g_agg);  fagg = (unsigned*)ptr;
        cudaGetSymbolAddress(&ptr, g_hin);  fhin = (unsigned*)ptr;
        cudaGetSymbolAddress(&ptr, g_pin);  fpin = (unsigned*)ptr;
        cudaGetSymbolAddress(&ptr, g_w);    fw   = (unsigned*)ptr;
        cudaGetSymbolAddress(&ptr, g_bias); fbias = (float*)ptr;
        cudaFuncSetAttribute(stream_gemm,
                             cudaFuncAttributeMaxDynamicSharedMemorySize, 72 * 1024);
    }
    #define WSLOT(s) (fw + (size_t)(s) * 8192)
    #define BIAS(n)  (fbias + (size_t)(n) * 64)

    auto Wm = [&](int i, int j){ return hm_W + (size_t)i * 320 * 64 + (size_t)j * 4096; };
    auto We = [&](int i, int j){ return eu_W + (size_t)i * 192 * 64 + (size_t)j * 4096; };
    auto hu1 = [&](int i){ return hu_W + (size_t)i * 8192; };
    auto hu2 = [&](int i){ return hu_W + (size_t)i * 8192 + 4096; };
    auto pu1 = [&](int i){ return pu_W + (size_t)i * 8192; };
    auto pu2 = [&](int i){ return pu_W + (size_t)i * 8192 + 4096; };

    unsigned *hc = base_h, *hn = base_h2;
    unsigned *pc = base_p, *pn = base_p2;
    unsigned *EAc = base_EA, *EAn = base_EA2;
    unsigned *EBc = base_EB, *EBn = base_EB2;

    const int EB256 = (EE + 255) / 256;
    const int GB = NP / 128;
    const int SB = (NN + 7) / 8;

    // ---- compose jobs ----
    Jobs J; memset(&J, 0, sizeof(J));
    int nj = 0;
    auto matJ = [&](const float* X, const float* Y, int slot, int k1, int wst) {
        J.j[nj].X = X; J.j[nj].Y = Y; J.j[nj].slot = WSLOT(slot);
        J.j[nj].k1 = k1; J.j[nj].wst = wst; J.j[nj].type = 0; nj++;
    };
    auto biasJ = [&](const float* X, const float* Y, const float* X2,
                     const float* Y2, float* bout) {
        J.j[nj].X = X; J.j[nj].Y = Y; J.j[nj].X2 = X2; J.j[nj].Y2 = Y2;
        J.j[nj].bout = bout; J.j[nj].type = 1; nj++;
    };
    for (int i = 0; i < LL; i++) {
        int nb = 54 + i * 13;
        matJ(hu1(i), We(i, 0), nb + 0, 64, 32);
        matJ(hu2(i), We(i, 0), nb + 1, 64, 32);
        matJ(hu1(i), We(i, 1), nb + 2, 64, 32);
        matJ(hu2(i), We(i, 1), nb + 3, 64, 32);
        biasJ(hu_b + i * 64, We(i, 0), nullptr, nullptr, BIAS(6 * i + 0));
        biasJ(hu_b + i * 64, We(i, 1), nullptr, nullptr, BIAS(6 * i + 1));
        if (i < 3) {
            matJ(pu1(i), Wm(i + 1, 1), nb + 9,  64, 32);
            matJ(pu2(i), Wm(i + 1, 1), nb + 10, 64, 32);
            matJ(pu1(i), Wm(i + 1, 3), nb + 11, 64, 32);
            matJ(pu2(i), Wm(i + 1, 3), nb + 12, 64, 32);
            biasJ(pu_b + i * 64, Wm(i + 1, 1), nullptr, nullptr, BIAS(6 * i + 4));
            biasJ(pu_b + i * 64, Wm(i + 1, 3), nullptr, nullptr, BIAS(6 * i + 5));
        }
    }
    matJ(he_W, Wm(0, 0), 106, 128, 64);
    matJ(he_W, Wm(0, 2), 107, 128, 64);
    matJ(pe_W, Wm(0, 1), 108, 16, 8);
    matJ(pe_W, Wm(0, 3), 109, 16, 8);
    biasJ(he_b, Wm(0, 0), pe_b, Wm(0, 1), BIAS(24));
    biasJ(he_b, Wm(0, 2), pe_b, Wm(0, 3), BIAS(25));

    // ---- GArgs helpers ----
    GArgs ga;
    auto clearG = [&]() { memset(&ga, 0, sizeof(ga)); };
    auto setY = [&](int y, void* C, const float* bias, int rm) {
        ga.C[y] = (unsigned*)C; ga.bias[y] = bias; ga.rmout[y] = rm; ga.nt[y] = 0;
    };
    auto addT = [&](int y, const unsigned* A, int Kst, unsigned* W, int Wst) {
        int tt = ga.nt[y];
        ga.A[y][tt] = A; ga.Kst[y][tt] = Kst;
        ga.W[y][tt] = W; ga.Wst[y][tt] = Wst; ga.nt[y] = tt + 1;
    };
    auto smemB = [&](int ny) {
        int mx = 0;
        for (int y = 0; y < ny; y++) {
            int s = 0;
            for (int tt = 0; tt < ga.nt[y]; tt++) s += 64 * (ga.Kst[y][tt] * 16 + 2);
            if (s > mx) mx = s;
        }
        return (size_t)mx * 4;
    };

    // ================= launches =================
    pack_weights<<<54, 256>>>(he_W, pe_W, hm_W, eu_W, pm_W, hu_W, pu_W);
    pack_inputs<<<(NN * 72 + 255) / 256, 256>>>(h_in, p_in);
    compose_mats<<<nj, 256>>>(J);

    // prologue: [h0(cm), p0(cm), S_h0(rm fp32), R_h0(rm fp32)]
    clearG();
    setY(0, hc, he_b, 0);       addT(0, fhin, 8, WSLOT(0), 64);
    setY(1, pc, pe_b, 0);       addT(1, fpin, 1, WSLOT(1), 8);
    setY(2, fS, BIAS(24), 1);   addT(2, fhin, 8, WSLOT(106), 64);
                                addT(2, fpin, 1, WSLOT(108), 8);
    setY(3, fR, BIAS(25), 1);   addT(3, fhin, 8, WSLOT(107), 64);
                                addT(3, fpin, 1, WSLOT(109), 8);
    stream_gemm<<<dim3(GB, 4), 256, smemB(4)>>>(ga);

    precompute_small<<<1, 1024>>>(ee_W, ee_b, hm_W, hm_b, eu_W, eu_b, pm_W, pm_b);
    deg_kernel<<<EB256, 256>>>(rec);
    scan_kernel<<<1, 1024>>>(NN);
    fill_kernel<<<EB256, 256>>>(send, rec);
    esum_csr<<<SB, 256>>>(e_in);

    // ================= layers =================
    for (int i = 0; i < LL; i++) {
        int b = 2 + i * 13;
        int nb = 54 + i * 13;

        spmm_kernel<<<SB, 256>>>(fagg, fS, fR, i, 0);

        // GA: [h'(cm), EA'(cm), EB'(cm)]
        clearG();
        setY(0, hn, hu_b + i * 64, 0);
        addT(0, hc, 4, WSLOT(b + 11), 64);
        addT(0, fagg, 4, WSLOT(b + 11) + 64, 64);
        setY(1, EAn, BIAS(6 * i + 0), 0);
        addT(1, hc, 4, WSLOT(nb + 0), 32);
        addT(1, fagg, 4, WSLOT(nb + 1), 32);
        if (i > 0) addT(1, EAc, 4, WSLOT(b + 7), 32);
        setY(2, EBn, BIAS(6 * i + 1), 0);
        addT(2, hc, 4, WSLOT(nb + 2), 32);
        addT(2, fagg, 4, WSLOT(nb + 3), 32);
        if (i > 0) addT(2, EBc, 4, WSLOT(b + 7), 32);
        stream_gemm<<<dim3(GB, 3), 256, smemB(3)>>>(ga);
        { unsigned* t1 = hc; hc = hn; hn = t1; }
        { unsigned* t1 = EAc; EAc = EAn; EAn = t1; }
        { unsigned* t1 = EBc; EBc = EBn; EBn = t1; }

        // pSR: [S_p(rm), R_p(rm)]
        clearG();
        setY(0, fS, nullptr, 1);
        addT(0, pc, 4, WSLOT(b + 8), 32);
        addT(0, EAc, 4, WSLOT(b + 10), 32);
        setY(1, fR, nullptr, 1);
        addT(1, pc, 4, WSLOT(b + 9), 32);
        addT(1, EBc, 4, WSLOT(b + 10), 32);
        stream_gemm<<<dim3(GB, 2), 256, smemB(2)>>>(ga);

        spmm_kernel<<<SB, 256>>>(fagg, fS, fR, i, 1);

        // GC: [p'(cm)] + next layer's [S_h(rm), R_h(rm)] via composed p'
        clearG();
        setY(0, pn, pu_b + i * 64, 0);
        addT(0, pc, 4, WSLOT(b + 12), 64);
        addT(0, fagg, 4, WSLOT(b + 12) + 64, 64);
        int ny = 1;
        if (i < 3) {
            int bj = 2 + (i + 1) * 13;
            setY(1, fS, BIAS(6 * i + 4), 1);
            addT(1, hc, 4, WSLOT(bj + 0), 32);
            addT(1, EAc, 4, WSLOT(bj + 4), 32);
            addT(1, pc, 4, WSLOT(nb + 9), 32);
            addT(1, fagg, 4, WSLOT(nb + 10), 32);
            setY(2, fR, BIAS(6 * i + 5), 1);
            addT(2, hc, 4, WSLOT(bj + 2), 32);
            addT(2, EBc, 4, WSLOT(bj + 4), 32);
            addT(2, pc, 4, WSLOT(nb + 11), 32);
            addT(2, fagg, 4, WSLOT(nb + 12), 32);
            ny = 3;
        }
        stream_gemm<<<dim3(GB, ny), 256, smemB(ny)>>>(ga);
        { unsigned* t1 = pc; pc = pn; pn = t1; }
    }

    // ----- output (transpose cm -> row-major) -----
    out_kernel<<<NP / 64, 256>>>((float*)d_out, hc, pc);
}

// round 13
// speedup vs baseline: 1.0214x; 1.0191x over previous
#include <cuda_runtime.h>
#include <cuda_bf16.h>

#define NN 50000
#define NP 50048
#define EE 800000
#define LL 4
#define MAXY 4
#define MAXT 4

// ---------------- storage ----------------
// col-major (pair-major) packed arrays: uint2 at (pair*NP + row)
__device__ unsigned g_h[NP * 64];
__device__ unsigned g_h2[NP * 64];
__device__ unsigned g_p[NP * 64];
__device__ unsigned g_p2[NP * 64];
__device__ unsigned g_EA[NP * 64];
__device__ unsigned g_EA2[NP * 64];
__device__ unsigned g_EB[NP * 64];
__device__ unsigned g_EB2[NP * 64];
__device__ unsigned g_agg[NP * 64];
__device__ unsigned g_hin[NP * 128];
__device__ unsigned g_pin[NP * 16];
// fp32 row-major (GEMM out -> spmm in)
__device__ float g_S[NP * 64];
__device__ float g_R[NP * 64];
__device__ unsigned g_w[110 * 8192];
__device__ float g_bias[26 * 64];
__device__ float g_esum[NN * 16];
__device__ int   g_deg[NN];
__device__ int   g_rowptr[NN + 1];
__device__ int   g_cursor[NN];
__device__ int   g_col[EE];
__device__ int   g_eid[EE];
__device__ float g_Gh[LL * 16 * 64];
__device__ float g_ch[LL * 64];
__device__ float g_Gp[LL * 16 * 64];
__device__ float g_cp[LL * 64];

// ---------------- helpers ----------------
__device__ __forceinline__ float2 unpk(uint2 v) {
    __nv_bfloat162 h = *(__nv_bfloat162*)&v.x;
    __nv_bfloat162 l = *(__nv_bfloat162*)&v.y;
    return make_float2(__bfloat162float(h.x) + __bfloat162float(l.x),
                       __bfloat162float(h.y) + __bfloat162float(l.y));
}
__device__ __forceinline__ uint2 pk(float a, float b) {
    __nv_bfloat162 hw = __floats2bfloat162_rn(a, b);
    float la = a - __bfloat162float(hw.x), lb = b - __bfloat162float(hw.y);
    __nv_bfloat162 lw = __floats2bfloat162_rn(la, lb);
    uint2 r; r.x = *(unsigned*)&hw; r.y = *(unsigned*)&lw; return r;
}
__device__ __forceinline__ void mma_bf16(float* d, const unsigned* a, const unsigned* b) {
    asm volatile(
        "mma.sync.aligned.m16n8k16.row.col.f32.bf16.bf16.f32 "
        "{%0,%1,%2,%3}, {%4,%5,%6,%7}, {%8,%9}, {%0,%1,%2,%3};"
        : "+f"(d[0]), "+f"(d[1]), "+f"(d[2]), "+f"(d[3])
        : "r"(a[0]), "r"(a[1]), "r"(a[2]), "r"(a[3]), "r"(b[0]), "r"(b[1]));
}
// cs for a term's weight smem column (words): conflict-free LDS.128 padding
__host__ __device__ __forceinline__ int csw(int kst) {
    return kst * 16 + ((kst & 1) ? 0 : 16);
}

// ---------------- setup kernels ----------------
__global__ __launch_bounds__(256) void out_kernel(float* __restrict__ out,
                                                  const unsigned* __restrict__ hc,
                                                  const unsigned* __restrict__ pc) {
    __shared__ float sh[64][66];
    __shared__ float sp[64][66];
    int r0 = blockIdx.x * 64;
    int t = threadIdx.x;
    #pragma unroll
    for (int it = 0; it < 8; it++) {
        int idx = t + it * 256;
        int rr = idx & 63, j = idx >> 6;
        float2 fh = unpk(*(const uint2*)&hc[((size_t)j * NP + r0 + rr) * 2]);
        float2 fp2 = unpk(*(const uint2*)&pc[((size_t)j * NP + r0 + rr) * 2]);
        sh[rr][2 * j] = fh.x; sh[rr][2 * j + 1] = fh.y;
        sp[rr][2 * j] = fp2.x; sp[rr][2 * j + 1] = fp2.y;
    }
    __syncthreads();
    #pragma unroll
    for (int it = 0; it < 16; it++) {
        int idx = t + it * 256;
        int c = idx & 63, rr = idx >> 6;
        int row = r0 + rr;
        if (row < NN) {
            out[(size_t)row * 64 + c] = sh[rr][c];
            out[(size_t)NN * 64 + (size_t)row * 64 + c] = sp[rr][c];
        }
    }
}

__global__ void pack_inputs(const float* __restrict__ h_in, const float* __restrict__ p_in) {
    int idx = blockIdx.x * blockDim.x + threadIdx.x;
    if (idx < NN) g_deg[idx] = 0;
    if (idx < NN * 64) {
        int pr = idx / NN, r = idx - pr * NN;
        float v0 = h_in[(size_t)r * 128 + 2 * pr];
        float v1 = h_in[(size_t)r * 128 + 2 * pr + 1];
        *(uint2*)&g_hin[((size_t)pr * NP + r) * 2] = pk(v0, v1);
    } else if (idx < NN * 64 + NN * 8) {
        int k = idx - NN * 64;
        int pr = k / NN, r = k - pr * NN;
        float v0 = p_in[(size_t)r * 16 + 2 * pr];
        float v1 = p_in[(size_t)r * 16 + 2 * pr + 1];
        *(uint2*)&g_pin[((size_t)pr * NP + r) * 2] = pk(v0, v1);
    }
}

// weight slots (col-major packed):
// slot 0: he_W, 1: pe_W; per layer i, b=2+i*13:
// +0 Wm_hs +1 Wm_ps +2 Wm_hr +3 Wm_pr +4 Wm_e +5 We_hs +6 We_hr +7 We_e
// +8 Wp_ps +9 Wp_pr +10 Wp_e +11 huW +12 puW
__global__ void pack_weights(const float* __restrict__ heW, const float* __restrict__ peW,
                             const float* __restrict__ hmW, const float* __restrict__ euW,
                             const float* __restrict__ pmW, const float* __restrict__ huW,
                             const float* __restrict__ puW) {
    int m = blockIdx.x;
    const float* src; int Kw;
    if (m == 0) { src = heW; Kw = 64; }
    else if (m == 1) { src = peW; Kw = 8; }
    else {
        int mm = m - 2, i = mm / 13, j = mm % 13;
        if (j < 5)       { src = hmW + (size_t)i * 20480 + j * 4096; Kw = 32; }
        else if (j < 8)  { src = euW + (size_t)i * 12288 + (j - 5) * 4096; Kw = 32; }
        else if (j < 10) { src = pmW + (size_t)i * 12288 + (j - 8) * 4096; Kw = 32; }
        else if (j == 10){ src = pmW + (size_t)i * 12288 + 2 * 4096; Kw = 32; }
        else if (j == 11){ src = huW + (size_t)i * 8192; Kw = 64; }
        else             { src = puW + (size_t)i * 8192; Kw = 64; }
    }
    unsigned* dst = g_w + (size_t)m * 8192;
    for (int idx = threadIdx.x; idx < 64 * Kw; idx += blockDim.x) {
        int c = idx & 63, k2 = idx >> 6;
        float v0 = src[(size_t)(2 * k2) * 64 + c];
        float v1 = src[(size_t)(2 * k2 + 1) * 64 + c];
        *(uint2*)&dst[(size_t)(c * Kw + k2) * 2] = pk(v0, v1);
    }
}

// ---------------- weight composition ----------------
struct Job {
    const float* X; const float* Y;
    const float* X2; const float* Y2;
    unsigned* slot; float* bout;
    int k1; int wst; int type;
};
struct Jobs { Job j[48]; };

__global__ __launch_bounds__(256) void compose_mats(Jobs ja) {
    Job jb = ja.j[blockIdx.x];
    __shared__ float sY[64 * 64];
    int t = threadIdx.x;
    if (jb.type == 0) {
        for (int i = t; i < 4096; i += 256) sY[i] = jb.Y[i];
        __syncthreads();
        int c = t & 63, mg = t >> 6;
        int kp = jb.k1 >> 1;
        for (int m = mg; m < kp; m += 4) {
            float z0 = 0.f, z1 = 0.f;
            const float* x0 = jb.X + (size_t)(2 * m) * 64;
            const float* x1 = x0 + 64;
            #pragma unroll 8
            for (int kk = 0; kk < 64; kk++) {
                float yv = sY[kk * 64 + c];
                z0 += x0[kk] * yv; z1 += x1[kk] * yv;
            }
            *(uint2*)&jb.slot[(size_t)(c * jb.wst + m) * 2] = pk(z0, z1);
        }
    } else {
        if (t < 64) {
            float s = 0.f;
            for (int kk = 0; kk < 64; kk++) s += jb.X[kk] * jb.Y[kk * 64 + t];
            if (jb.X2)
                for (int kk = 0; kk < 64; kk++) s += jb.X2[kk] * jb.Y2[kk * 64 + t];
            jb.bout[t] = s;
        }
    }
}

// ---------------- CSR build ----------------
__global__ void deg_kernel(const int* __restrict__ rec) {
    int j = blockIdx.x * blockDim.x + threadIdx.x;
    if (j < EE) atomicAdd(&g_deg[rec[j]], 1);
}
__global__ __launch_bounds__(1024) void scan_kernel(int n) {
    __shared__ int wsum[32];
    __shared__ int carry;
    int t = threadIdx.x, lane = t & 31, wid = t >> 5;
    if (t == 0) { carry = 0; g_rowptr[0] = 0; g_cursor[0] = 0; }
    __syncthreads();
    for (int base = 0; base < n; base += 1024) {
        int i = base + t;
        int v = (i < n) ? g_deg[i] : 0;
        int x = v;
        #pragma unroll
        for (int o = 1; o < 32; o <<= 1) {
            int y = __shfl_up_sync(0xffffffffu, x, o);
            if (lane >= o) x += y;
        }
        if (lane == 31) wsum[wid] = x;
        __syncthreads();
        if (wid == 0) {
            int s = wsum[lane];
            #pragma unroll
            for (int o = 1; o < 32; o <<= 1) {
                int y = __shfl_up_sync(0xffffffffu, s, o);
                if (lane >= o) s += y;
            }
            wsum[lane] = s;
        }
        __syncthreads();
        int off = carry + (wid ? wsum[wid - 1] : 0);
        if (i < n) {
            g_rowptr[i + 1] = off + x;
            if (i + 1 < n) g_cursor[i + 1] = off + x;
        }
        __syncthreads();
        if (t == 0) carry += wsum[31];
        __syncthreads();
    }
}
__global__ void fill_kernel(const int* __restrict__ send, const int* __restrict__ rec) {
    int j = blockIdx.x * blockDim.x + threadIdx.x;
    if (j < EE) {
        int pos = atomicAdd(&g_cursor[rec[j]], 1);
        g_col[pos] = send[j];
        g_eid[pos] = j;
    }
}
__global__ __launch_bounds__(256) void esum_csr(const float* __restrict__ e_in) {
    int t = threadIdx.x;
    int node = blockIdx.x * 8 + (t >> 5);
    if (node >= NN) return;
    int lane = t & 31;
    int beg = g_rowptr[node], end = g_rowptr[node + 1];
    float v = 0.f;
    for (int e = beg + (lane >> 4); e < end; e += 2)
        v += e_in[(size_t)g_eid[e] * 16 + (lane & 15)];
    v += __shfl_down_sync(0xffffffffu, v, 16);
    if (lane < 16) g_esum[node * 16 + lane] = v;
}

// ---------------- precompute per-layer small matrices ----------------
__global__ __launch_bounds__(1024) void precompute_small(
    const float* __restrict__ eeW, const float* __restrict__ eeb,
    const float* __restrict__ hmW, const float* __restrict__ hmb,
    const float* __restrict__ euW, const float* __restrict__ eub,
    const float* __restrict__ pmW, const float* __restrict__ pmb)
{
    __shared__ float sEW[1024], sec[64], sEW2[1024], sec2[64];
    int t = threadIdx.x;
    int r = t >> 6, c = t & 63;
    sEW[t] = eeW[t];
    if (t < 64) sec[t] = eeb[t];
    __syncthreads();
    for (int i = 0; i < LL; i++) {
        const float* Wm_e = hmW + (size_t)i * 320 * 64 + 256 * 64;
        const float* We_e = euW + (size_t)i * 192 * 64 + 128 * 64;
        const float* Wp_e = pmW + (size_t)i * 192 * 64 + 128 * 64;
        float s = 0.f;
        #pragma unroll 8
        for (int k = 0; k < 64; k++) s += sEW[r * 64 + k] * Wm_e[k * 64 + c];
        g_Gh[i * 1024 + t] = s;
        if (t < 64) {
            float s2 = hmb[i * 64 + t];
            for (int k = 0; k < 64; k++) s2 += sec[k] * Wm_e[k * 64 + t];
            g_ch[i * 64 + t] = s2;
        }
        s = 0.f;
        #pragma unroll 8
        for (int k = 0; k < 64; k++) s += sEW[r * 64 + k] * We_e[k * 64 + c];
        sEW2[t] = s;
        if (t < 64) {
            float s2 = eub[i * 64 + t];
            for (int k = 0; k < 64; k++) s2 += sec[k] * We_e[k * 64 + t];
            sec2[t] = s2;
        }
        __syncthreads();
        sEW[t] = sEW2[t];
        if (t < 64) sec[t] = sec2[t];
        __syncthreads();
        s = 0.f;
        #pragma unroll 8
        for (int k = 0; k < 64; k++) s += sEW[r * 64 + k] * Wp_e[k * 64 + c];
        g_Gp[i * 1024 + t] = s;
        if (t < 64) {
            float s2 = pmb[i * 64 + t];
            for (int k = 0; k < 64; k++) s2 += sec[k] * Wp_e[k * 64 + t];
            g_cp[i * 64 + t] = s2;
        }
        __syncthreads();
    }
}

// ---------------- multi-output streaming tensor-core GEMM ----------------
// A: col-major packed uint2 at (pair*NP + row).
// Weight smem: column c occupies cs=csw(kst) words; pair p (ks=p>>3, q=p&3,
// h=(p>>2)&1) stored at word c*cs + ks*16 + q*4 + h*2 (hi at +0, lo at +1).
// Lane loads uint4 at c*cs + ks*16 + q*4 -> {b0h, b0l, b1h, b1l}.
// Conflict-free: cs/4 ≡ 4 (mod 8) for even kst, 4 (mod 8) for kst=1 (cs=16).
struct GArgs {
    const unsigned* A[MAXY][MAXT];
    const unsigned* W[MAXY][MAXT];
    int Kst[MAXY][MAXT];
    int Wst[MAXY][MAXT];
    int nt[MAXY];
    unsigned* C[MAXY];
    const float* bias[MAXY];
    int rmout[MAXY];
};

__global__ __launch_bounds__(256) void stream_gemm(GArgs ga) {
    extern __shared__ unsigned sW[];
    int y = blockIdx.y;
    int t = threadIdx.x;
    int w = t >> 5, lane = t & 31;
    int wm = w >> 1, wn = w & 1;
    int gq = lane >> 2, q = lane & 3;
    int nt = ga.nt[y];

    // ---- stage weights (pair-reordered, conflict-free layout) ----
    int off = 0;
    for (int tm = 0; tm < nt; tm++) {
        const unsigned* Wg = ga.W[y][tm];
        int kst = ga.Kst[y][tm];
        int Tp = kst * 8;
        int cs = csw(kst);
        int wst = ga.Wst[y][tm];
        for (int idx = t; idx < 64 * Tp; idx += 256) {
            int c = idx / Tp, p = idx - c * Tp;
            int ks = p >> 3, qq = p & 3, hh = (p >> 2) & 1;
            uint2 v = *(const uint2*)&Wg[(size_t)(c * wst + p) * 2];
            int word = off + c * cs + ks * 16 + qq * 4 + hh * 2;
            sW[word] = v.x;
            sW[word + 1] = v.y;
        }
        off += 64 * cs;
    }
    __syncthreads();

    float acc[2][4][4];
    #pragma unroll
    for (int mt = 0; mt < 2; mt++)
        #pragma unroll
        for (int ntI = 0; ntI < 4; ntI++)
            #pragma unroll
            for (int i = 0; i < 4; i++) acc[mt][ntI][i] = 0.f;

    int rowb = blockIdx.x * 128 + wm * 32 + gq;

    off = 0;
    for (int tm = 0; tm < nt; tm++) {
        const unsigned* A = ga.A[y][tm];
        int kst = ga.Kst[y][tm];
        int cs = csw(kst);
        const unsigned* wsm = sW + off;
        for (int ks = 0; ks < kst; ks++) {
            int pb = ks * 8 + q;
            unsigned ah[2][4], al[2][4];
            #pragma unroll
            for (int mt = 0; mt < 2; mt++) {
                int r = rowb + mt * 16;
                uint2 v0 = *(const uint2*)&A[((size_t)pb * NP + r) * 2];
                uint2 v1 = *(const uint2*)&A[((size_t)pb * NP + r + 8) * 2];
                uint2 v2 = *(const uint2*)&A[((size_t)(pb + 4) * NP + r) * 2];
                uint2 v3 = *(const uint2*)&A[((size_t)(pb + 4) * NP + r + 8) * 2];
                ah[mt][0] = v0.x; al[mt][0] = v0.y;
                ah[mt][1] = v1.x; al[mt][1] = v1.y;
                ah[mt][2] = v2.x; al[mt][2] = v2.y;
                ah[mt][3] = v3.x; al[mt][3] = v3.y;
            }
            #pragma unroll
            for (int ntI = 0; ntI < 4; ntI++) {
                int c = wn * 32 + ntI * 8 + gq;
                uint4 bv = *(const uint4*)&wsm[c * cs + ks * 16 + q * 4];
                unsigned bh[2] = {bv.x, bv.z};
                unsigned bl[2] = {bv.y, bv.w};
                #pragma unroll
                for (int mt = 0; mt < 2; mt++) {
                    mma_bf16(acc[mt][ntI], ah[mt], bh);
                    mma_bf16(acc[mt][ntI], ah[mt], bl);
                    mma_bf16(acc[mt][ntI], al[mt], bh);
                }
            }
        }
        off += 64 * cs;
    }

    unsigned* C = ga.C[y];
    const float* bias = ga.bias[y];
    int rm = ga.rmout[y];
    #pragma unroll
    for (int ntI = 0; ntI < 4; ntI++) {
        int cb = wn * 32 + ntI * 8 + q * 2;
        float bx = bias ? bias[cb] : 0.f;
        float by = bias ? bias[cb + 1] : 0.f;
        #pragma unroll
        for (int mt = 0; mt < 2; mt++) {
            int row = blockIdx.x * 128 + wm * 32 + mt * 16 + gq;
            float a0 = acc[mt][ntI][0] + bx, a1 = acc[mt][ntI][1] + by;
            float a2 = acc[mt][ntI][2] + bx, a3 = acc[mt][ntI][3] + by;
            if (rm) {
                float* Cf = (float*)C;
                if (row < NN)
                    *(float2*)&Cf[(size_t)row * 64 + cb] = make_float2(a0, a1);
                if (row + 8 < NN)
                    *(float2*)&Cf[(size_t)(row + 8) * 64 + cb] = make_float2(a2, a3);
            } else {
                size_t pbase = (size_t)(cb >> 1) * NP;
                if (row < NN)
                    *(uint2*)&C[(pbase + row) * 2] = pk(a0, a1);
                if (row + 8 < NN)
                    *(uint2*)&C[(pbase + row + 8) * 2] = pk(a2, a3);
            }
        }
    }
}

// ---------------- SpMM: fp32 S/R in (row-major), packed col-major agg out ----------------
__global__ __launch_bounds__(256) void spmm_kernel(
    unsigned* __restrict__ agg, const float* __restrict__ S,
    const float* __restrict__ R, int layer, int pbranch)
{
    __shared__ float sG[16 * 64];
    __shared__ float sc[64];
    int t = threadIdx.x;
    const float* G = (pbranch ? g_Gp : g_Gh) + layer * 1024;
    const float* cc = (pbranch ? g_cp : g_ch) + layer * 64;
    for (int i = t; i < 1024; i += 256) sG[i] = G[i];
    if (t < 64) sc[t] = cc[t];
    __syncthreads();
    int node = blockIdx.x * 8 + (t >> 5);
    if (node >= NN) return;
    int lane = t & 31;
    int beg = g_rowptr[node], end = g_rowptr[node + 1];
    const float2* S2 = (const float2*)S;
    float ax = 0.f, ay = 0.f;
    int e = beg;
    for (; e + 4 <= end; e += 4) {
        int u0 = g_col[e], u1 = g_col[e + 1], u2 = g_col[e + 2], u3 = g_col[e + 3];
        float2 f0 = S2[(size_t)u0 * 32 + lane];
        float2 f1 = S2[(size_t)u1 * 32 + lane];
        float2 f2 = S2[(size_t)u2 * 32 + lane];
        float2 f3 = S2[(size_t)u3 * 32 + lane];
        ax += (f0.x + f1.x) + (f2.x + f3.x);
        ay += (f0.y + f1.y) + (f2.y + f3.y);
    }
    for (; e < end; e++) {
        float2 f = S2[(size_t)g_col[e] * 32 + lane];
        ax += f.x; ay += f.y;
    }
    float deg = (float)(end - beg);
    int c0 = lane * 2;
    float2 r2 = ((const float2*)R)[(size_t)node * 32 + lane];
    float t0 = deg * (r2.x + sc[c0]) + ax;
    float t1 = deg * (r2.y + sc[c0 + 1]) + ay;
    #pragma unroll
    for (int k = 0; k < 16; k++) {
        float ev = g_esum[node * 16 + k];
        t0 += ev * sG[k * 64 + c0];
        t1 += ev * sG[k * 64 + c0 + 1];
    }
    *(uint2*)&agg[((size_t)lane * NP + node) * 2] = pk(t0, t1);
}

// ---------------- host ----------------
extern "C" void kernel_launch(void* const* d_in, const int* in_sizes, int n_in,
                              void* d_out, int out_size)
{
    const float* h_in = (const float*)d_in[0];
    const float* e_in = (const float*)d_in[1];
    const float* p_in = (const float*)d_in[2];
    const int*   ei   = (const int*)d_in[3];
    const int* send = ei;
    const int* rec  = ei + EE;
    const float* he_W = (const float*)d_in[4];
    const float* he_b = (const float*)d_in[5];
    const float* ee_W = (const float*)d_in[6];
    const float* ee_b = (const float*)d_in[7];
    const float* pe_W = (const float*)d_in[8];
    const float* pe_b = (const float*)d_in[9];
    const float* hm_W = (const float*)d_in[10];
    const float* hm_b = (const float*)d_in[11];
    const float* hu_W = (const float*)d_in[12];
    const float* hu_b = (const float*)d_in[13];
    const float* eu_W = (const float*)d_in[14];
    const float* eu_b = (const float*)d_in[15];
    const float* pm_W = (const float*)d_in[16];
    const float* pm_b = (const float*)d_in[17];
    const float* pu_W = (const float*)d_in[18];
    const float* pu_b = (const float*)d_in[19];

    static unsigned* base_h = nullptr;
    static unsigned *base_h2, *base_p, *base_p2, *base_EA, *base_EA2,
                    *base_EB, *base_EB2, *fagg, *fhin, *fpin, *fw;
    static float *fS, *fR, *fbias;
    if (base_h == nullptr) {
        void* ptr;
        cudaGetSymbolAddress(&ptr, g_h);    base_h   = (unsigned*)ptr;
        cudaGetSymbolAddress(&ptr, g_h2);   base_h2  = (unsigned*)ptr;
        cudaGetSymbolAddress(&ptr, g_p);    base_p   = (unsigned*)ptr;
        cudaGetSymbolAddress(&ptr, g_p2);   base_p2  = (unsigned*)ptr;
        cudaGetSymbolAddress(&ptr, g_EA);   base_EA  = (unsigned*)ptr;
        cudaGetSymbolAddress(&ptr, g_EA2);  base_EA2 = (unsigned*)ptr;
        cudaGetSymbolAddress(&ptr, g_EB);   base_EB  = (unsigned*)ptr;
        cudaGetSymbolAddress(&ptr, g_EB2);  base_EB2 = (unsigned*)ptr;
        cudaGetSymbolAddress(&ptr, g_S);    fS   = (float*)ptr;
        cudaGetSymbolAddress(&ptr, g_R);    fR   = (float*)ptr;
        cudaGetSymbolAddress(&ptr, g_agg);  fagg = (unsigned*)ptr;
        cudaGetSymbolAddress(&ptr, g_hin);  fhin = (unsigned*)ptr;
        cudaGetSymbolAddress(&ptr, g_pin);  fpin = (unsigned*)ptr;
        cudaGetSymbolAddress(&ptr, g_w);    fw   = (unsigned*)ptr;
        cudaGetSymbolAddress(&ptr, g_bias); fbias = (float*)ptr;
        cudaFuncSetAttribute(stream_gemm,
                             cudaFuncAttributeMaxDynamicSharedMemorySize, 88 * 1024);
    }
    #define WSLOT(s) (fw + (size_t)(s) * 8192)
    #define BIAS(n)  (fbias + (size_t)(n) * 64)

    auto Wm = [&](int i, int j){ return hm_W + (size_t)i * 320 * 64 + (size_t)j * 4096; };
    auto We = [&](int i, int j){ return eu_W + (size_t)i * 192 * 64 + (size_t)j * 4096; };
    auto hu1 = [&](int i){ return hu_W + (size_t)i * 8192; };
    auto hu2 = [&](int i){ return hu_W + (size_t)i * 8192 + 4096; };
    auto pu1 = [&](int i){ return pu_W + (size_t)i * 8192; };
    auto pu2 = [&](int i){ return pu_W + (size_t)i * 8192 + 4096; };

    unsigned *hc = base_h, *hn = base_h2;
    unsigned *pc = base_p, *pn = base_p2;
    unsigned *EAc = base_EA, *EAn = base_EA2;
    unsigned *EBc = base_EB, *EBn = base_EB2;

    const int EB256 = (EE + 255) / 256;
    const int GB = NP / 128;
    const int SB = (NN + 7) / 8;

    // ---- compose jobs ----
    Jobs J; memset(&J, 0, sizeof(J));
    int nj = 0;
    auto matJ = [&](const float* X, const float* Y, int slot, int k1, int wst) {
        J.j[nj].X = X; J.j[nj].Y = Y; J.j[nj].slot = WSLOT(slot);
        J.j[nj].k1 = k1; J.j[nj].wst = wst; J.j[nj].type = 0; nj++;
    };
    auto biasJ = [&](const float* X, const float* Y, const float* X2,
                     const float* Y2, float* bout) {
        J.j[nj].X = X; J.j[nj].Y = Y; J.j[nj].X2 = X2; J.j[nj].Y2 = Y2;
        J.j[nj].bout = bout; J.j[nj].type = 1; nj++;
    };
    for (int i = 0; i < LL; i++) {
        int nb = 54 + i * 13;
        matJ(hu1(i), We(i, 0), nb + 0, 64, 32);
        matJ(hu2(i), We(i, 0), nb + 1, 64, 32);
        matJ(hu1(i), We(i, 1), nb + 2, 64, 32);
        matJ(hu2(i), We(i, 1), nb + 3, 64, 32);
        biasJ(hu_b + i * 64, We(i, 0), nullptr, nullptr, BIAS(6 * i + 0));
        biasJ(hu_b + i * 64, We(i, 1), nullptr, nullptr, BIAS(6 * i + 1));
        if (i < 3) {
            matJ(pu1(i), Wm(i + 1, 1), nb + 9,  64, 32);
            matJ(pu2(i), Wm(i + 1, 1), nb + 10, 64, 32);
            matJ(pu1(i), Wm(i + 1, 3), nb + 11, 64, 32);
            matJ(pu2(i), Wm(i + 1, 3), nb + 12, 64, 32);
            biasJ(pu_b + i * 64, Wm(i + 1, 1), nullptr, nullptr, BIAS(6 * i + 4));
            biasJ(pu_b + i * 64, Wm(i + 1, 3), nullptr, nullptr, BIAS(6 * i + 5));
        }
    }
    matJ(he_W, Wm(0, 0), 106, 128, 64);
    matJ(he_W, Wm(0, 2), 107, 128, 64);
    matJ(pe_W, Wm(0, 1), 108, 16, 8);
    matJ(pe_W, Wm(0, 3), 109, 16, 8);
    biasJ(he_b, Wm(0, 0), pe_b, Wm(0, 1), BIAS(24));
    biasJ(he_b, Wm(0, 2), pe_b, Wm(0, 3), BIAS(25));

    // ---- GArgs helpers ----
    GArgs ga;
    auto clearG = [&]() { memset(&ga, 0, sizeof(ga)); };
    auto setY = [&](int y, void* C, const float* bias, int rm) {
        ga.C[y] = (unsigned*)C; ga.bias[y] = bias; ga.rmout[y] = rm; ga.nt[y] = 0;
    };
    auto addT = [&](int y, const unsigned* A, int Kst, unsigned* W, int Wst) {
        int tt = ga.nt[y];
        ga.A[y][tt] = A; ga.Kst[y][tt] = Kst;
        ga.W[y][tt] = W; ga.Wst[y][tt] = Wst; ga.nt[y] = tt + 1;
    };
    auto smemB = [&](int ny) {
        int mx = 0;
        for (int y = 0; y < ny; y++) {
            int s = 0;
            for (int tt = 0; tt < ga.nt[y]; tt++) s += 64 * csw(ga.Kst[y][tt]);
            if (s > mx) mx = s;
        }
        return (size_t)mx * 4;
    };

    // ================= launches =================
    pack_weights<<<54, 256>>>(he_W, pe_W, hm_W, eu_W, pm_W, hu_W, pu_W);
    pack_inputs<<<(NN * 72 + 255) / 256, 256>>>(h_in, p_in);
    compose_mats<<<nj, 256>>>(J);

    // prologue: [h0(cm), p0(cm), S_h0(rm fp32), R_h0(rm fp32)]
    clearG();
    setY(0, hc, he_b, 0);       addT(0, fhin, 8, WSLOT(0), 64);
    setY(1, pc, pe_b, 0);       addT(1, fpin, 1, WSLOT(1), 8);
    setY(2, fS, BIAS(24), 1);   addT(2, fhin, 8, WSLOT(106), 64);
                                addT(2, fpin, 1, WSLOT(108), 8);
    setY(3, fR, BIAS(25), 1);   addT(3, fhin, 8, WSLOT(107), 64);
                                addT(3, fpin, 1, WSLOT(109), 8);
    stream_gemm<<<dim3(GB, 4), 256, smemB(4)>>>(ga);

    precompute_small<<<1, 1024>>>(ee_W, ee_b, hm_W, hm_b, eu_W, eu_b, pm_W, pm_b);
    deg_kernel<<<EB256, 256>>>(rec);
    scan_kernel<<<1, 1024>>>(NN);
    fill_kernel<<<EB256, 256>>>(send, rec);
    esum_csr<<<SB, 256>>>(e_in);

    // ================= layers =================
    for (int i = 0; i < LL; i++) {
        int b = 2 + i * 13;
        int nb = 54 + i * 13;

        spmm_kernel<<<SB, 256>>>(fagg, fS, fR, i, 0);

        // GA: [h'(cm), EA'(cm), EB'(cm)]
        clearG();
        setY(0, hn, hu_b + i * 64, 0);
        addT(0, hc, 4, WSLOT(b + 11), 64);
        addT(0, fagg, 4, WSLOT(b + 11) + 64, 64);
        setY(1, EAn, BIAS(6 * i + 0), 0);
        addT(1, hc, 4, WSLOT(nb + 0), 32);
        addT(1, fagg, 4, WSLOT(nb + 1), 32);
        if (i > 0) addT(1, EAc, 4, WSLOT(b + 7), 32);
        setY(2, EBn, BIAS(6 * i + 1), 0);
        addT(2, hc, 4, WSLOT(nb + 2), 32);
        addT(2, fagg, 4, WSLOT(nb + 3), 32);
        if (i > 0) addT(2, EBc, 4, WSLOT(b + 7), 32);
        stream_gemm<<<dim3(GB, 3), 256, smemB(3)>>>(ga);
        { unsigned* t1 = hc; hc = hn; hn = t1; }
        { unsigned* t1 = EAc; EAc = EAn; EAn = t1; }
        { unsigned* t1 = EBc; EBc = EBn; EBn = t1; }

        // pSR: [S_p(rm), R_p(rm)]
        clearG();
        setY(0, fS, nullptr, 1);
        addT(0, pc, 4, WSLOT(b + 8), 32);
        addT(0, EAc, 4, WSLOT(b + 10), 32);
        setY(1, fR, nullptr, 1);
        addT(1, pc, 4, WSLOT(b + 9), 32);
        addT(1, EBc, 4, WSLOT(b + 10), 32);
        stream_gemm<<<dim3(GB, 2), 256, smemB(2)>>>(ga);

        spmm_kernel<<<SB, 256>>>(fagg, fS, fR, i, 1);

        // GC: [p'(cm)] + next layer's [S_h(rm), R_h(rm)] via composed p'
        clearG();
        setY(0, pn, pu_b + i * 64, 0);
        addT(0, pc, 4, WSLOT(b + 12), 64);
        addT(0, fagg, 4, WSLOT(b + 12) + 64, 64);
        int ny = 1;
        if (i < 3) {
            int bj = 2 + (i + 1) * 13;
            setY(1, fS, BIAS(6 * i + 4), 1);
            addT(1, hc, 4, WSLOT(bj + 0), 32);
            addT(1, EAc, 4, WSLOT(bj + 4), 32);
            addT(1, pc, 4, WSLOT(nb + 9), 32);
            addT(1, fagg, 4, WSLOT(nb + 10), 32);
            setY(2, fR, BIAS(6 * i + 5), 1);
            addT(2, hc, 4, WSLOT(bj + 2), 32);
            addT(2, EBc, 4, WSLOT(bj + 4), 32);
            addT(2, pc, 4, WSLOT(nb + 11), 32);
            addT(2, fagg, 4, WSLOT(nb + 12), 32);
            ny = 3;
        }
        stream_gemm<<<dim3(GB, ny), 256, smemB(ny)>>>(ga);
        { unsigned* t1 = pc; pc = pn; pn = t1; }
    }

    // ----- output (transpose cm -> row-major) -----
    out_kernel<<<NP / 64, 256>>>((float*)d_out, hc, pc);
}

// round 17
// speedup vs baseline: 1.1978x; 1.1727x over previous
#include <cuda_runtime.h>
#include <cuda_bf16.h>

#define NN 50000
#define NP 50176            // 196 * 256
#define EE 800000
#define LL 4
#define MAXY 5
#define MAXT 4

// ---------------- storage ----------------
// col-major (pair-major) packed arrays: uint2 at (pair*NP + row)
__device__ unsigned g_h[NP * 64];
__device__ unsigned g_h2[NP * 64];
__device__ unsigned g_p[NP * 64];
__device__ unsigned g_p2[NP * 64];
__device__ unsigned g_EA[NP * 64];
__device__ unsigned g_EA2[NP * 64];
__device__ unsigned g_EB[NP * 64];
__device__ unsigned g_EB2[NP * 64];
__device__ unsigned g_agg[NP * 64];
__device__ unsigned g_hin[NP * 128];
__device__ unsigned g_pin[NP * 16];
// fp32 row-major (GEMM out -> spmm in)
__device__ float g_S[NP * 64];
__device__ float g_R[NP * 64];
// weights: fragment-linear packed layout (see pack_weights)
__device__ unsigned g_w[110 * 8192];
__device__ float g_cw[16 * 4096];
__device__ float g_bias[26 * 64];
__device__ float g_esum[NN * 16];
__device__ int   g_deg[NN];
__device__ int   g_rowptr[NN + 1];
__device__ int   g_cursor[NN];
__device__ int   g_col[EE];
__device__ int   g_eid[EE];
__device__ float g_Gh[LL * 16 * 64];
__device__ float g_ch[LL * 64];
__device__ float g_Gp[LL * 16 * 64];
__device__ float g_cp[LL * 64];

// ---------------- helpers ----------------
__device__ __forceinline__ float2 unpk(uint2 v) {
    __nv_bfloat162 h = *(__nv_bfloat162*)&v.x;
    __nv_bfloat162 l = *(__nv_bfloat162*)&v.y;
    return make_float2(__bfloat162float(h.x) + __bfloat162float(l.x),
                       __bfloat162float(h.y) + __bfloat162float(l.y));
}
__device__ __forceinline__ uint2 pk(float a, float b) {
    __nv_bfloat162 hw = __floats2bfloat162_rn(a, b);
    float la = a - __bfloat162float(hw.x), lb = b - __bfloat162float(hw.y);
    __nv_bfloat162 lw = __floats2bfloat162_rn(la, lb);
    uint2 r; r.x = *(unsigned*)&hw; r.y = *(unsigned*)&lw; return r;
}
__device__ __forceinline__ void mma_bf16(float* d, const unsigned* a, const unsigned* b) {
    asm volatile(
        "mma.sync.aligned.m16n8k16.row.col.f32.bf16.bf16.f32 "
        "{%0,%1,%2,%3}, {%4,%5,%6,%7}, {%8,%9}, {%0,%1,%2,%3};"
        : "+f"(d[0]), "+f"(d[1]), "+f"(d[2]), "+f"(d[3])
        : "r"(a[0]), "r"(a[1]), "r"(a[2]), "r"(a[3]), "r"(b[0]), "r"(b[1]));
}
// fragment-linear word offset for pair k2 within a column (col stride = Kw*2)
__host__ __device__ __forceinline__ int fragoff(int k2) {
    return (k2 >> 3) * 16 + (k2 & 3) * 4 + ((k2 >> 2) & 1) * 2;
}

// ---------------- setup kernels ----------------
__global__ __launch_bounds__(256) void out_kernel(float* __restrict__ out,
                                                  const unsigned* __restrict__ hc,
                                                  const unsigned* __restrict__ pc) {
    __shared__ float sh[64][66];
    __shared__ float sp[64][66];
    int r0 = blockIdx.x * 64;
    if (r0 >= NN) return;
    int t = threadIdx.x;
    #pragma unroll
    for (int it = 0; it < 8; it++) {
        int idx = t + it * 256;
        int rr = idx & 63, j = idx >> 6;
        float2 fh = unpk(*(const uint2*)&hc[((size_t)j * NP + r0 + rr) * 2]);
        float2 fp2 = unpk(*(const uint2*)&pc[((size_t)j * NP + r0 + rr) * 2]);
        sh[rr][2 * j] = fh.x; sh[rr][2 * j + 1] = fh.y;
        sp[rr][2 * j] = fp2.x; sp[rr][2 * j + 1] = fp2.y;
    }
    __syncthreads();
    #pragma unroll
    for (int it = 0; it < 16; it++) {
        int idx = t + it * 256;
        int c = idx & 63, rr = idx >> 6;
        int row = r0 + rr;
        if (row < NN) {
            out[(size_t)row * 64 + c] = sh[rr][c];
            out[(size_t)NN * 64 + (size_t)row * 64 + c] = sp[rr][c];
        }
    }
}

__global__ void zero_deg() {
    int i = blockIdx.x * blockDim.x + threadIdx.x;
    if (i < NN) g_deg[i] = 0;
}

__global__ void pack_inputs(const float* __restrict__ h_in, const float* __restrict__ p_in) {
    int idx = blockIdx.x * blockDim.x + threadIdx.x;
    if (idx < NN * 64) {
        int pr = idx / NN, r = idx - pr * NN;
        float v0 = h_in[(size_t)r * 128 + 2 * pr];
        float v1 = h_in[(size_t)r * 128 + 2 * pr + 1];
        *(uint2*)&g_hin[((size_t)pr * NP + r) * 2] = pk(v0, v1);
    } else if (idx < NN * 64 + NN * 8) {
        int k = idx - NN * 64;
        int pr = k / NN, r = k - pr * NN;
        float v0 = p_in[(size_t)r * 16 + 2 * pr];
        float v1 = p_in[(size_t)r * 16 + 2 * pr + 1];
        *(uint2*)&g_pin[((size_t)pr * NP + r) * 2] = pk(v0, v1);
    }
}

// weight slots, fragment-linear: word = c*(Kw*2) + fragoff(k2); hi at +0, lo at +1.
// slot 0: he_W (Kw=64), 1: pe_W (Kw=8); per layer i, b=2+i*13:
// +0..+10 as before (Kw=32); +11 huW split into 2 half-slots (+0, +4096 words);
// +12 puW likewise.
__global__ void pack_weights(const float* __restrict__ heW, const float* __restrict__ peW,
                             const float* __restrict__ hmW, const float* __restrict__ euW,
                             const float* __restrict__ pmW, const float* __restrict__ huW,
                             const float* __restrict__ puW) {
    int m = blockIdx.x;
    const float* src; int Kw; int split = 0;
    if (m == 0) { src = heW; Kw = 64; }
    else if (m == 1) { src = peW; Kw = 8; }
    else {
        int mm = m - 2, i = mm / 13, j = mm % 13;
        if (j < 5)       { src = hmW + (size_t)i * 20480 + j * 4096; Kw = 32; }
        else if (j < 8)  { src = euW + (size_t)i * 12288 + (j - 5) * 4096; Kw = 32; }
        else if (j < 10) { src = pmW + (size_t)i * 12288 + (j - 8) * 4096; Kw = 32; }
        else if (j == 10){ src = pmW + (size_t)i * 12288 + 2 * 4096; Kw = 32; }
        else if (j == 11){ src = huW + (size_t)i * 8192; Kw = 64; split = 1; }
        else             { src = puW + (size_t)i * 8192; Kw = 64; split = 1; }
    }
    unsigned* dst = g_w + (size_t)m * 8192;
    for (int idx = threadIdx.x; idx < 64 * Kw; idx += blockDim.x) {
        int c = idx & 63, k2 = idx >> 6;
        float v0 = src[(size_t)(2 * k2) * 64 + c];
        float v1 = src[(size_t)(2 * k2 + 1) * 64 + c];
        uint2 v = pk(v0, v1);
        int word;
        if (split) {
            int half = k2 >> 5, kk = k2 & 31;
            word = half * 4096 + c * 64 + fragoff(kk);
        } else {
            word = c * (Kw * 2) + fragoff(k2);
        }
        dst[word] = v.x;
        dst[word + 1] = v.y;
    }
}

// ---------------- weight composition ----------------
// type 0: Z[k1,64] = X@Y -> slot (fragment-linear, wst pairs/col), optional fp32 ws
// type 1: bout = X@Y (+ X2@Y2)
struct Job {
    const float* X; const float* Y;
    const float* X2; const float* Y2;
    unsigned* slot; float* ws; float* bout;
    int k1; int wst; int type;
};
struct Jobs { Job j[52]; };

__global__ __launch_bounds__(256) void compose_mats(Jobs ja) {
    Job jb = ja.j[blockIdx.x];
    __shared__ float sY[64 * 64];
    int t = threadIdx.x;
    if (jb.type == 0) {
        for (int i = t; i < 4096; i += 256) sY[i] = jb.Y[i];
        __syncthreads();
        int c = t & 63, mg = t >> 6;
        int kp = jb.k1 >> 1;
        for (int m = mg; m < kp; m += 4) {
            float z0 = 0.f, z1 = 0.f;
            const float* x0 = jb.X + (size_t)(2 * m) * 64;
            const float* x1 = x0 + 64;
            #pragma unroll 8
            for (int kk = 0; kk < 64; kk++) {
                float yv = sY[kk * 64 + c];
                z0 += x0[kk] * yv; z1 += x1[kk] * yv;
            }
            uint2 v = pk(z0, z1);
            int word = c * (jb.wst * 2) + fragoff(m);
            jb.slot[word] = v.x;
            jb.slot[word + 1] = v.y;
            if (jb.ws) {
                jb.ws[(size_t)(2 * m) * 64 + c] = z0;
                jb.ws[(size_t)(2 * m + 1) * 64 + c] = z1;
            }
        }
    } else {
        if (t < 64) {
            float s = 0.f;
            for (int kk = 0; kk < 64; kk++) s += jb.X[kk] * jb.Y[kk * 64 + t];
            if (jb.X2)
                for (int kk = 0; kk < 64; kk++) s += jb.X2[kk] * jb.Y2[kk * 64 + t];
            jb.bout[t] = s;
        }
    }
}

// ---------------- CSR build ----------------
__global__ void deg_kernel(const int* __restrict__ rec) {
    int j = blockIdx.x * blockDim.x + threadIdx.x;
    if (j < EE) atomicAdd(&g_deg[rec[j]], 1);
}
__global__ __launch_bounds__(1024) void scan_kernel(int n) {
    __shared__ int wsum[32];
    __shared__ int carry;
    int t = threadIdx.x, lane = t & 31, wid = t >> 5;
    if (t == 0) { carry = 0; g_rowptr[0] = 0; g_cursor[0] = 0; }
    __syncthreads();
    for (int base = 0; base < n; base += 1024) {
        int i = base + t;
        int v = (i < n) ? g_deg[i] : 0;
        int x = v;
        #pragma unroll
        for (int o = 1; o < 32; o <<= 1) {
            int y = __shfl_up_sync(0xffffffffu, x, o);
            if (lane >= o) x += y;
        }
        if (lane == 31) wsum[wid] = x;
        __syncthreads();
        if (wid == 0) {
            int s = wsum[lane];
            #pragma unroll
            for (int o = 1; o < 32; o <<= 1) {
                int y = __shfl_up_sync(0xffffffffu, s, o);
                if (lane >= o) s += y;
            }
            wsum[lane] = s;
        }
        __syncthreads();
        int off = carry + (wid ? wsum[wid - 1] : 0);
        if (i < n) {
            g_rowptr[i + 1] = off + x;
            if (i + 1 < n) g_cursor[i + 1] = off + x;
        }
        __syncthreads();
        if (t == 0) carry += wsum[31];
        __syncthreads();
    }
}
__global__ void fill_kernel(const int* __restrict__ send, const int* __restrict__ rec) {
    int j = blockIdx.x * blockDim.x + threadIdx.x;
    if (j < EE) {
        int pos = atomicAdd(&g_cursor[rec[j]], 1);
        g_col[pos] = send[j];
        g_eid[pos] = j;
    }
}
__global__ __launch_bounds__(256) void esum_csr(const float* __restrict__ e_in) {
    int t = threadIdx.x;
    int node = blockIdx.x * 8 + (t >> 5);
    if (node >= NN) return;
    int lane = t & 31;
    int beg = g_rowptr[node], end = g_rowptr[node + 1];
    float v = 0.f;
    for (int e = beg + (lane >> 4); e < end; e += 2)
        v += e_in[(size_t)g_eid[e] * 16 + (lane & 15)];
    v += __shfl_down_sync(0xffffffffu, v, 16);
    if (lane < 16) g_esum[node * 16 + lane] = v;
}

// ---------------- precompute per-layer small matrices ----------------
__global__ __launch_bounds__(1024) void precompute_small(
    const float* __restrict__ eeW, const float* __restrict__ eeb,
    const float* __restrict__ hmW, const float* __restrict__ hmb,
    const float* __restrict__ euW, const float* __restrict__ eub,
    const float* __restrict__ pmW, const float* __restrict__ pmb)
{
    __shared__ float sEW[1024], sec[64], sEW2[1024], sec2[64];
    int t = threadIdx.x;
    int r = t >> 6, c = t & 63;
    sEW[t] = eeW[t];
    if (t < 64) sec[t] = eeb[t];
    __syncthreads();
    for (int i = 0; i < LL; i++) {
        const float* Wm_e = hmW + (size_t)i * 320 * 64 + 256 * 64;
        const float* We_e = euW + (size_t)i * 192 * 64 + 128 * 64;
        const float* Wp_e = pmW + (size_t)i * 192 * 64 + 128 * 64;
        float s = 0.f;
        #pragma unroll 8
        for (int k = 0; k < 64; k++) s += sEW[r * 64 + k] * Wm_e[k * 64 + c];
        g_Gh[i * 1024 + t] = s;
        if (t < 64) {
            float s2 = hmb[i * 64 + t];
            for (int k = 0; k < 64; k++) s2 += sec[k] * Wm_e[k * 64 + t];
            g_ch[i * 64 + t] = s2;
        }
        s = 0.f;
        #pragma unroll 8
        for (int k = 0; k < 64; k++) s += sEW[r * 64 + k] * We_e[k * 64 + c];
        sEW2[t] = s;
        if (t < 64) {
            float s2 = eub[i * 64 + t];
            for (int k = 0; k < 64; k++) s2 += sec[k] * We_e[k * 64 + t];
            sec2[t] = s2;
        }
        __syncthreads();
        sEW[t] = sEW2[t];
        if (t < 64) sec[t] = sec2[t];
        __syncthreads();
        s = 0.f;
        #pragma unroll 8
        for (int k = 0; k < 64; k++) s += sEW[r * 64 + k] * Wp_e[k * 64 + c];
        g_Gp[i * 1024 + t] = s;
        if (t < 64) {
            float s2 = pmb[i * 64 + t];
            for (int k = 0; k < 64; k++) s2 += sec[k] * Wp_e[k * 64 + t];
            g_cp[i * 64 + t] = s2;
        }
        __syncthreads();
    }
}

// ---------------- multi-output streaming tensor-core GEMM ----------------
// 256-row tiles, 8 warps (wm 0..3 x wn 0..1), mt 0..3 per warp.
// A: cm packed uint2 at (pair*NP + row). W: fragment-linear global (LDG.128,
// L1-resident). No smem, no syncs.
struct GArgs {
    const unsigned* A[MAXY][MAXT];
    const unsigned* W[MAXY][MAXT];
    int Kst[MAXY][MAXT];
    int nt[MAXY];
    unsigned* C[MAXY];
    const float* bias[MAXY];
    int rmout[MAXY];
};

__global__ __launch_bounds__(256, 2) void stream_gemm(GArgs ga) {
    int y = blockIdx.y;
    int t = threadIdx.x;
    int w = t >> 5, lane = t & 31;
    int wm = w >> 1, wn = w & 1;
    int gq = lane >> 2, q = lane & 3;
    int nt = ga.nt[y];

    float acc[4][4][4];
    #pragma unroll
    for (int mt = 0; mt < 4; mt++)
        #pragma unroll
        for (int ntI = 0; ntI < 4; ntI++)
            #pragma unroll
            for (int i = 0; i < 4; i++) acc[mt][ntI][i] = 0.f;

    int rowb = blockIdx.x * 256 + wm * 64 + gq;

    for (int tm = 0; tm < nt; tm++) {
        const unsigned* A = ga.A[y][tm];
        const unsigned* Wg = ga.W[y][tm];
        int kst = ga.Kst[y][tm];
        int wstr = kst * 16;   // words per weight column
        for (int ks = 0; ks < kst; ks++) {
            int pb = ks * 8 + q;
            unsigned ah[4][4], al[4][4];
            #pragma unroll
            for (int mt = 0; mt < 4; mt++) {
                int r = rowb + mt * 16;
                uint2 v0 = *(const uint2*)&A[((size_t)pb * NP + r) * 2];
                uint2 v1 = *(const uint2*)&A[((size_t)pb * NP + r + 8) * 2];
                uint2 v2 = *(const uint2*)&A[((size_t)(pb + 4) * NP + r) * 2];
                uint2 v3 = *(const uint2*)&A[((size_t)(pb + 4) * NP + r + 8) * 2];
                ah[mt][0] = v0.x; al[mt][0] = v0.y;
                ah[mt][1] = v1.x; al[mt][1] = v1.y;
                ah[mt][2] = v2.x; al[mt][2] = v2.y;
                ah[mt][3] = v3.x; al[mt][3] = v3.y;
            }
            #pragma unroll
            for (int ntI = 0; ntI < 4; ntI++) {
                int c = wn * 32 + ntI * 8 + gq;
                uint4 bv = *(const uint4*)&Wg[(size_t)c * wstr + ks * 16 + q * 4];
                unsigned bh[2] = {bv.x, bv.z};
                unsigned bl[2] = {bv.y, bv.w};
                #pragma unroll
                for (int mt = 0; mt < 4; mt++) {
                    mma_bf16(acc[mt][ntI], ah[mt], bh);
                    mma_bf16(acc[mt][ntI], ah[mt], bl);
                    mma_bf16(acc[mt][ntI], al[mt], bh);
                }
            }
        }
    }

    unsigned* C = ga.C[y];
    const float* bias = ga.bias[y];
    int rm = ga.rmout[y];
    #pragma unroll
    for (int ntI = 0; ntI < 4; ntI++) {
        int cb = wn * 32 + ntI * 8 + q * 2;
        float bx = bias ? bias[cb] : 0.f;
        float by = bias ? bias[cb + 1] : 0.f;
        #pragma unroll
        for (int mt = 0; mt < 4; mt++) {
            int row = blockIdx.x * 256 + wm * 64 + mt * 16 + gq;
            float a0 = acc[mt][ntI][0] + bx, a1 = acc[mt][ntI][1] + by;
            float a2 = acc[mt][ntI][2] + bx, a3 = acc[mt][ntI][3] + by;
            if (rm) {
                float* Cf = (float*)C;
                if (row < NN)
                    *(float2*)&Cf[(size_t)row * 64 + cb] = make_float2(a0, a1);
                if (row + 8 < NN)
                    *(float2*)&Cf[(size_t)(row + 8) * 64 + cb] = make_float2(a2, a3);
            } else {
                size_t pbase = (size_t)(cb >> 1) * NP;
                if (row < NN)
                    *(uint2*)&C[(pbase + row) * 2] = pk(a0, a1);
                if (row + 8 < NN)
                    *(uint2*)&C[(pbase + row + 8) * 2] = pk(a2, a3);
            }
        }
    }
}

// ---------------- SpMM ----------------
__global__ __launch_bounds__(256) void spmm_kernel(
    unsigned* __restrict__ agg, const float* __restrict__ S,
    const float* __restrict__ R, int layer, int pbranch)
{
    __shared__ float sG[16 * 64];
    __shared__ float sc[64];
    int t = threadIdx.x;
    const float* G = (pbranch ? g_Gp : g_Gh) + layer * 1024;
    const float* cc = (pbranch ? g_cp : g_ch) + layer * 64;
    for (int i = t; i < 1024; i += 256) sG[i] = G[i];
    if (t < 64) sc[t] = cc[t];
    __syncthreads();
    int node = blockIdx.x * 8 + (t >> 5);
    if (node >= NN) return;
    int lane = t & 31;
    int beg = g_rowptr[node], end = g_rowptr[node + 1];
    const float2* S2 = (const float2*)S;
    float ax = 0.f, ay = 0.f;
    int e = beg;
    for (; e + 4 <= end; e += 4) {
        int u0 = g_col[e], u1 = g_col[e + 1], u2 = g_col[e + 2], u3 = g_col[e + 3];
        float2 f0 = S2[(size_t)u0 * 32 + lane];
        float2 f1 = S2[(size_t)u1 * 32 + lane];
        float2 f2 = S2[(size_t)u2 * 32 + lane];
        float2 f3 = S2[(size_t)u3 * 32 + lane];
        ax += (f0.x + f1.x) + (f2.x + f3.x);
        ay += (f0.y + f1.y) + (f2.y + f3.y);
    }
    for (; e < end; e++) {
        float2 f = S2[(size_t)g_col[e] * 32 + lane];
        ax += f.x; ay += f.y;
    }
    float deg = (float)(end - beg);
    int c0 = lane * 2;
    float2 r2 = ((const float2*)R)[(size_t)node * 32 + lane];
    float t0 = deg * (r2.x + sc[c0]) + ax;
    float t1 = deg * (r2.y + sc[c0 + 1]) + ay;
    #pragma unroll
    for (int k = 0; k < 16; k++) {
        float ev = g_esum[node * 16 + k];
        t0 += ev * sG[k * 64 + c0];
        t1 += ev * sG[k * 64 + c0 + 1];
    }
    *(uint2*)&agg[((size_t)lane * NP + node) * 2] = pk(t0, t1);
}

// ---------------- host ----------------
extern "C" void kernel_launch(void* const* d_in, const int* in_sizes, int n_in,
                              void* d_out, int out_size)
{
    const float* h_in = (const float*)d_in[0];
    const float* e_in = (const float*)d_in[1];
    const float* p_in = (const float*)d_in[2];
    const int*   ei   = (const int*)d_in[3];
    const int* send = ei;
    const int* rec  = ei + EE;
    const float* he_W = (const float*)d_in[4];
    const float* he_b = (const float*)d_in[5];
    const float* ee_W = (const float*)d_in[6];
    const float* ee_b = (const float*)d_in[7];
    const float* pe_W = (const float*)d_in[8];
    const float* pe_b = (const float*)d_in[9];
    const float* hm_W = (const float*)d_in[10];
    const float* hm_b = (const float*)d_in[11];
    const float* hu_W = (const float*)d_in[12];
    const float* hu_b = (const float*)d_in[13];
    const float* eu_W = (const float*)d_in[14];
    const float* eu_b = (const float*)d_in[15];
    const float* pm_W = (const float*)d_in[16];
    const float* pm_b = (const float*)d_in[17];
    const float* pu_W = (const float*)d_in[18];
    const float* pu_b = (const float*)d_in[19];

    static unsigned* base_h = nullptr;
    static unsigned *base_h2, *base_p, *base_p2, *base_EA, *base_EA2,
                    *base_EB, *base_EB2, *fagg, *fhin, *fpin, *fw;
    static float *fS, *fR, *fbias, *fcw;
    static cudaStream_t s2;
    static cudaEvent_t evF, evJ;
    if (base_h == nullptr) {
        void* ptr;
        cudaGetSymbolAddress(&ptr, g_h);    base_h   = (unsigned*)ptr;
        cudaGetSymbolAddress(&ptr, g_h2);   base_h2  = (unsigned*)ptr;
        cudaGetSymbolAddress(&ptr, g_p);    base_p   = (unsigned*)ptr;
        cudaGetSymbolAddress(&ptr, g_p2);   base_p2  = (unsigned*)ptr;
        cudaGetSymbolAddress(&ptr, g_EA);   base_EA  = (unsigned*)ptr;
        cudaGetSymbolAddress(&ptr, g_EA2);  base_EA2 = (unsigned*)ptr;
        cudaGetSymbolAddress(&ptr, g_EB);   base_EB  = (unsigned*)ptr;
        cudaGetSymbolAddress(&ptr, g_EB2);  base_EB2 = (unsigned*)ptr;
        cudaGetSymbolAddress(&ptr, g_S);    fS   = (float*)ptr;
        cudaGetSymbolAddress(&ptr, g_R);    fR   = (float*)ptr;
        cudaGetSymbolAddress(&ptr, g_agg);  fagg = (unsigned*)ptr;
        cudaGetSymbolAddress(&ptr, g_hin);  fhin = (unsigned*)ptr;
        cudaGetSymbolAddress(&ptr, g_pin);  fpin = (unsigned*)ptr;
        cudaGetSymbolAddress(&ptr, g_w);    fw   = (unsigned*)ptr;
        cudaGetSymbolAddress(&ptr, g_bias); fbias = (float*)ptr;
        cudaGetSymbolAddress(&ptr, g_cw);   fcw  = (float*)ptr;
        cudaStreamCreateWithFlags(&s2, cudaStreamNonBlocking);
        cudaEventCreateWithFlags(&evF, cudaEventDisableTiming);
        cudaEventCreateWithFlags(&evJ, cudaEventDisableTiming);
    }
    #define WSLOT(s) (fw + (size_t)(s) * 8192)
    #define BIAS(n)  (fbias + (size_t)(n) * 64)
    #define CW(n)    (fcw + (size_t)(n) * 4096)

    auto Wm = [&](int i, int j){ return hm_W + (size_t)i * 320 * 64 + (size_t)j * 4096; };
    auto We = [&](int i, int j){ return eu_W + (size_t)i * 192 * 64 + (size_t)j * 4096; };
    auto Wp = [&](int i, int j){ return pm_W + (size_t)i * 192 * 64 + (size_t)j * 4096; };
    auto hu1 = [&](int i){ return hu_W + (size_t)i * 8192; };
    auto hu2 = [&](int i){ return hu_W + (size_t)i * 8192 + 4096; };
    auto pu1 = [&](int i){ return pu_W + (size_t)i * 8192; };
    auto pu2 = [&](int i){ return pu_W + (size_t)i * 8192 + 4096; };

    unsigned *hc = base_h, *hn = base_h2;
    unsigned *pc = base_p, *pn = base_p2;
    unsigned *EAc = base_EA, *EAn = base_EA2;
    unsigned *EBc = base_EB, *EBn = base_EB2;

    const int EB256 = (EE + 255) / 256;
    const int GB = NP / 256;   // 196
    const int SB = (NN + 7) / 8;

    // ---- compose job tables ----
    Jobs JA; memset(&JA, 0, sizeof(JA));
    int na = 0;
    auto matJ = [&](Jobs& J, int& n, const float* X, const float* Y,
                    int slot, int sub, float* ws, int k1, int wst) {
        J.j[n].X = X; J.j[n].Y = Y; J.j[n].slot = WSLOT(slot) + sub;
        J.j[n].ws = ws; J.j[n].k1 = k1; J.j[n].wst = wst; J.j[n].type = 0; n++;
    };
    auto biasJ = [&](Jobs& J, int& n, const float* X, const float* Y,
                     const float* X2, const float* Y2, float* bout) {
        J.j[n].X = X; J.j[n].Y = Y; J.j[n].X2 = X2; J.j[n].Y2 = Y2;
        J.j[n].bout = bout; J.j[n].type = 1; n++;
    };
    for (int i = 0; i < LL; i++) {
        int nb = 54 + i * 13;
        matJ(JA, na, hu1(i), We(i, 0), nb + 0, 0, CW(i * 4 + 0), 64, 32);
        matJ(JA, na, hu2(i), We(i, 0), nb + 1, 0, CW(i * 4 + 1), 64, 32);
        matJ(JA, na, hu1(i), We(i, 1), nb + 2, 0, CW(i * 4 + 2), 64, 32);
        matJ(JA, na, hu2(i), We(i, 1), nb + 3, 0, CW(i * 4 + 3), 64, 32);
        matJ(JA, na, We(i, 2), Wp(i, 2), nb + 4, 0, nullptr, 64, 32);
        biasJ(JA, na, hu_b + i * 64, We(i, 0), nullptr, nullptr, BIAS(6 * i + 0));
        biasJ(JA, na, hu_b + i * 64, We(i, 1), nullptr, nullptr, BIAS(6 * i + 1));
        if (i < 3) {
            matJ(JA, na, pu1(i), Wm(i + 1, 1), nb + 9,  0, nullptr, 64, 32);
            matJ(JA, na, pu2(i), Wm(i + 1, 1), nb + 10, 0, nullptr, 64, 32);
            matJ(JA, na, pu1(i), Wm(i + 1, 3), nb + 11, 0, nullptr, 64, 32);
            matJ(JA, na, pu2(i), Wm(i + 1, 3), nb + 12, 0, nullptr, 64, 32);
            biasJ(JA, na, pu_b + i * 64, Wm(i + 1, 1), nullptr, nullptr, BIAS(6 * i + 4));
            biasJ(JA, na, pu_b + i * 64, Wm(i + 1, 3), nullptr, nullptr, BIAS(6 * i + 5));
        }
    }
    matJ(JA, na, he_W, Wm(0, 0), 106, 0, nullptr, 128, 64);
    matJ(JA, na, he_W, Wm(0, 2), 107, 0, nullptr, 128, 64);
    matJ(JA, na, pe_W, Wm(0, 1), 108, 0, nullptr, 16, 8);
    matJ(JA, na, pe_W, Wm(0, 3), 109, 0, nullptr, 16, 8);
    biasJ(JA, na, he_b, Wm(0, 0), pe_b, Wm(0, 1), BIAS(24));
    biasJ(JA, na, he_b, Wm(0, 2), pe_b, Wm(0, 3), BIAS(25));   // na = 52

    Jobs JB; memset(&JB, 0, sizeof(JB));
    int nbj = 0;
    for (int i = 0; i < LL; i++) {
        int nb = 54 + i * 13;
        matJ(JB, nbj, CW(i * 4 + 0), Wp(i, 2), nb + 5, 0, nullptr, 64, 32);
        matJ(JB, nbj, CW(i * 4 + 1), Wp(i, 2), nb + 6, 0, nullptr, 64, 32);
        matJ(JB, nbj, CW(i * 4 + 2), Wp(i, 2), nb + 7, 0, nullptr, 64, 32);
        matJ(JB, nbj, CW(i * 4 + 3), Wp(i, 2), nb + 8, 0, nullptr, 64, 32);
        biasJ(JB, nbj, BIAS(6 * i + 0), Wp(i, 2), nullptr, nullptr, BIAS(6 * i + 2));
        biasJ(JB, nbj, BIAS(6 * i + 1), Wp(i, 2), nullptr, nullptr, BIAS(6 * i + 3));
    }   // nbj = 24

    // ---- GArgs helpers ----
    GArgs ga;
    auto clearG = [&]() { memset(&ga, 0, sizeof(ga)); };
    auto setY = [&](int y, void* C, const float* bias, int rm) {
        ga.C[y] = (unsigned*)C; ga.bias[y] = bias; ga.rmout[y] = rm; ga.nt[y] = 0;
    };
    auto addT = [&](int y, const unsigned* A, int Kst, unsigned* W) {
        int tt = ga.nt[y];
        ga.A[y][tt] = A; ga.Kst[y][tt] = Kst; ga.W[y][tt] = W; ga.nt[y] = tt + 1;
    };

    // ================= forked setup =================
    cudaEventRecord(evF, 0);
    cudaStreamWaitEvent(s2, evF, 0);
    // branch B (stream s2): CSR + small-matrix precompute
    zero_deg<<<(NN + 255) / 256, 256, 0, s2>>>();
    deg_kernel<<<EB256, 256, 0, s2>>>(rec);
    scan_kernel<<<1, 1024, 0, s2>>>(NN);
    fill_kernel<<<EB256, 256, 0, s2>>>(send, rec);
    esum_csr<<<SB, 256, 0, s2>>>(e_in);
    precompute_small<<<1, 1024, 0, s2>>>(ee_W, ee_b, hm_W, hm_b, eu_W, eu_b, pm_W, pm_b);
    cudaEventRecord(evJ, s2);

    // branch A (stream 0): packs + composition + prologue
    pack_weights<<<54, 256>>>(he_W, pe_W, hm_W, eu_W, pm_W, hu_W, pu_W);
    pack_inputs<<<(NN * 72 + 255) / 256, 256>>>(h_in, p_in);
    compose_mats<<<na, 256>>>(JA);
    compose_mats<<<nbj, 256>>>(JB);

    // prologue: [h0(cm), p0(cm), S_h0(rm), R_h0(rm)]
    clearG();
    setY(0, hc, he_b, 0);       addT(0, fhin, 8, WSLOT(0));
    setY(1, pc, pe_b, 0);       addT(1, fpin, 1, WSLOT(1));
    setY(2, fS, BIAS(24), 1);   addT(2, fhin, 8, WSLOT(106));
                                addT(2, fpin, 1, WSLOT(108));
    setY(3, fR, BIAS(25), 1);   addT(3, fhin, 8, WSLOT(107));
                                addT(3, fpin, 1, WSLOT(109));
    stream_gemm<<<dim3(GB, 4), 256>>>(ga);

    cudaStreamWaitEvent(0, evJ, 0);   // join

    // ================= layers =================
    for (int i = 0; i < LL; i++) {
        int b = 2 + i * 13;
        int nb = 54 + i * 13;

        spmm_kernel<<<SB, 256>>>(fagg, fS, fR, i, 0);

        // GA5: [h'(cm), EA'(cm), EB'(cm), S_p(rm), R_p(rm)]
        clearG();
        setY(0, hn, hu_b + i * 64, 0);
        addT(0, hc, 4, WSLOT(b + 11));
        addT(0, fagg, 4, WSLOT(b + 11) + 4096);
        setY(1, EAn, BIAS(6 * i + 0), 0);
        addT(1, hc, 4, WSLOT(nb + 0));
        addT(1, fagg, 4, WSLOT(nb + 1));
        if (i > 0) addT(1, EAc, 4, WSLOT(b + 7));
        setY(2, EBn, BIAS(6 * i + 1), 0);
        addT(2, hc, 4, WSLOT(nb + 2));
        addT(2, fagg, 4, WSLOT(nb + 3));
        if (i > 0) addT(2, EBc, 4, WSLOT(b + 7));
        setY(3, fS, BIAS(6 * i + 2), 1);
        addT(3, pc, 4, WSLOT(b + 8));
        addT(3, hc, 4, WSLOT(nb + 5));
        addT(3, fagg, 4, WSLOT(nb + 6));
        if (i > 0) addT(3, EAc, 4, WSLOT(nb + 4));
        setY(4, fR, BIAS(6 * i + 3), 1);
        addT(4, pc, 4, WSLOT(b + 9));
        addT(4, hc, 4, WSLOT(nb + 7));
        addT(4, fagg, 4, WSLOT(nb + 8));
        if (i > 0) addT(4, EBc, 4, WSLOT(nb + 4));
        stream_gemm<<<dim3(GB, 5), 256>>>(ga);
        { unsigned* t1 = hc; hc = hn; hn = t1; }
        { unsigned* t1 = EAc; EAc = EAn; EAn = t1; }
        { unsigned* t1 = EBc; EBc = EBn; EBn = t1; }

        spmm_kernel<<<SB, 256>>>(fagg, fS, fR, i, 1);

        // GC: [p'(cm)] + next layer's [S_h(rm), R_h(rm)] via composed p'
        clearG();
        setY(0, pn, pu_b + i * 64, 0);
        addT(0, pc, 4, WSLOT(b + 12));
        addT(0, fagg, 4, WSLOT(b + 12) + 4096);
        int ny = 1;
        if (i < 3) {
            int bj = 2 + (i + 1) * 13;
            setY(1, fS, BIAS(6 * i + 4), 1);
            addT(1, hc, 4, WSLOT(bj + 0));
            addT(1, EAc, 4, WSLOT(bj + 4));
            addT(1, pc, 4, WSLOT(nb + 9));
            addT(1, fagg, 4, WSLOT(nb + 10));
            setY(2, fR, BIAS(6 * i + 5), 1);
            addT(2, hc, 4, WSLOT(bj + 2));
            addT(2, EBc, 4, WSLOT(bj + 4));
            addT(2, pc, 4, WSLOT(nb + 11));
            addT(2, fagg, 4, WSLOT(nb + 12));
            ny = 3;
        }
        stream_gemm<<<dim3(GB, ny), 256>>>(ga);
        { unsigned* t1 = pc; pc = pn; pn = t1; }
    }

    // ----- output (transpose cm -> row-major) -----
    out_kernel<<<(NN + 63) / 64, 256>>>((float*)d_out, hc, pc);
}